// round 1
// baseline (speedup 1.0000x reference)
#include <cuda_runtime.h>
#include <math.h>

#define D_MODEL 512
#define N_TOK   1024
#define BATCH   2
#define HEADS   8
#define HIDDEN  2048
#define M_ROWS  (BATCH * N_TOK)   // 2048

// ---------------- scratch (static device globals; no allocation) ----------------
__device__ float g_xln[M_ROWS * D_MODEL];        // LN1 out, reused for LN2 out
__device__ float g_qkv[M_ROWS * 3 * D_MODEL];
__device__ float g_att[M_ROWS * D_MODEL];        // attention output (B,N,H*d)
__device__ float g_x2 [M_ROWS * D_MODEL];        // x + attn_proj (residual stream)
__device__ float g_hid[M_ROWS * HIDDEN];         // gelu(fc1)

// ---------------- LayerNorm: one block per row (512 cols, 256 threads) ----------
__global__ void ln_kernel(const float* __restrict__ x, const float* __restrict__ g,
                          const float* __restrict__ b, float* __restrict__ y) {
    int row = blockIdx.x;
    const float* xr = x + (size_t)row * D_MODEL;
    int t = threadIdx.x;
    float v0 = xr[t];
    float v1 = xr[t + 256];

    __shared__ float sh[8], sh2[8];
    int w = t >> 5, lane = t & 31;

    float s = v0 + v1;
    #pragma unroll
    for (int o = 16; o; o >>= 1) s += __shfl_xor_sync(0xffffffffu, s, o);
    if (lane == 0) sh[w] = s;
    __syncthreads();
    float mean = (sh[0]+sh[1]+sh[2]+sh[3]+sh[4]+sh[5]+sh[6]+sh[7]) * (1.0f / D_MODEL);

    float d0 = v0 - mean, d1 = v1 - mean;
    float q = d0 * d0 + d1 * d1;
    #pragma unroll
    for (int o = 16; o; o >>= 1) q += __shfl_xor_sync(0xffffffffu, q, o);
    if (lane == 0) sh2[w] = q;
    __syncthreads();
    float var = (sh2[0]+sh2[1]+sh2[2]+sh2[3]+sh2[4]+sh2[5]+sh2[6]+sh2[7]) * (1.0f / D_MODEL);
    float inv = rsqrtf(var + 1e-5f);

    float* yr = y + (size_t)row * D_MODEL;
    yr[t]       = d0 * inv * g[t]       + b[t];
    yr[t + 256] = d1 * inv * g[t + 256] + b[t + 256];
}

// ---------------- SGEMM: C[M,N] = A[M,K] @ B[K,N] + bias (+gelu) (+res) --------
// Tiles: BM=128, BN=64, BK=16. 256 threads as 16x16, each 8x4 micro-tile.
__global__ void gemm_kernel(const float* __restrict__ A, const float* __restrict__ B,
                            const float* __restrict__ bias, const float* __restrict__ res,
                            float* __restrict__ C, int M, int Nn, int K, int do_gelu) {
    __shared__ float As[16 * 128];   // transposed: As[k][m]
    __shared__ float Bs[16 * 64];    // Bs[k][n]

    int tid = threadIdx.x;
    int tx = tid & 15, ty = tid >> 4;
    int m0 = blockIdx.y * 128, n0 = blockIdx.x * 64;

    float acc[8][4];
    #pragma unroll
    for (int i = 0; i < 8; i++)
        #pragma unroll
        for (int j = 0; j < 4; j++) acc[i][j] = 0.0f;

    for (int k0 = 0; k0 < K; k0 += 16) {
        // A tile: 128 rows x 16 cols = 512 float4s, 2 per thread (transpose store)
        #pragma unroll
        for (int u = 0; u < 2; u++) {
            int f = tid + u * 256;
            int r = f >> 2, c = (f & 3) * 4;
            float4 av = *(const float4*)(A + (size_t)(m0 + r) * K + k0 + c);
            As[(c + 0) * 128 + r] = av.x;
            As[(c + 1) * 128 + r] = av.y;
            As[(c + 2) * 128 + r] = av.z;
            As[(c + 3) * 128 + r] = av.w;
        }
        // B tile: 16 rows x 64 cols = 256 float4s, 1 per thread
        {
            int r = tid >> 4, c = (tid & 15) * 4;
            *(float4*)(Bs + r * 64 + c) = *(const float4*)(B + (size_t)(k0 + r) * Nn + n0 + c);
        }
        __syncthreads();

        #pragma unroll
        for (int kk = 0; kk < 16; kk++) {
            float4 a0 = *(const float4*)(As + kk * 128 + ty * 8);
            float4 a1 = *(const float4*)(As + kk * 128 + ty * 8 + 4);
            float4 bv = *(const float4*)(Bs + kk * 64 + tx * 4);
            float a[8] = {a0.x, a0.y, a0.z, a0.w, a1.x, a1.y, a1.z, a1.w};
            float bb[4] = {bv.x, bv.y, bv.z, bv.w};
            #pragma unroll
            for (int i = 0; i < 8; i++)
                #pragma unroll
                for (int j = 0; j < 4; j++) acc[i][j] = fmaf(a[i], bb[j], acc[i][j]);
        }
        __syncthreads();
    }

    #pragma unroll
    for (int i = 0; i < 8; i++) {
        int m = m0 + ty * 8 + i;
        #pragma unroll
        for (int j = 0; j < 4; j++) {
            int n = n0 + tx * 4 + j;
            float v = acc[i][j] + bias[n];
            if (do_gelu) v = 0.5f * v * (1.0f + erff(v * 0.70710678118654752f));
            if (res) v += res[(size_t)m * Nn + n];
            C[(size_t)m * Nn + n] = v;
        }
    }
}

// ---------------- Flash attention with distance bias ---------------------------
// bias[b,h,n,m] = ||coords[b,n]-coords[b,m]|| * w_edge[2,h]  (frame average collapses)
// grid: (N/64 query tiles, H, B); 256 threads = 16(tx over keys) x 16(ty over queries)
__global__ void attn_kernel(const float* __restrict__ qkv, const float* __restrict__ coords,
                            const unsigned char* __restrict__ mask,
                            const float* __restrict__ w_edge, float* __restrict__ out) {
    extern __shared__ float sm[];
    float* Qs  = sm;                 // [64 d][65 q]  (transposed, padded)
    float* Ks  = sm + 64 * 65;       // [64 d][65 k]; reused as Ps [64 q][65 k]
    float* Vs  = Ks + 64 * 65;       // [64 k][64 d]
    float* kcx = Vs + 64 * 64;       // 64
    float* kcy = kcx + 64;           // 64

    int b = blockIdx.z, h = blockIdx.y;
    int n0 = blockIdx.x * 64;
    int tid = threadIdx.x, tx = tid & 15, ty = tid >> 4;
    const float we = w_edge[2 * HEADS + h];
    const float scale = 0.125f;      // 64^-0.5
    const int C3 = 3 * D_MODEL;

    // Q tile (scaled), transposed into smem
    for (int i = tid; i < 4096; i += 256) {
        int r = i >> 6, c = i & 63;
        Qs[c * 65 + r] = qkv[(size_t)(b * N_TOK + n0 + r) * C3 + h * 64 + c] * scale;
    }
    float qx[4], qy[4];
    #pragma unroll
    for (int i = 0; i < 4; i++) {
        int n = n0 + ty * 4 + i;
        qx[i] = coords[(size_t)(b * N_TOK + n) * 2];
        qy[i] = coords[(size_t)(b * N_TOK + n) * 2 + 1];
    }

    float mrun[4], lrun[4], O[4][4];
    #pragma unroll
    for (int i = 0; i < 4; i++) {
        mrun[i] = -3.0e38f; lrun[i] = 0.0f;
        #pragma unroll
        for (int j = 0; j < 4; j++) O[i][j] = 0.0f;
    }

    const unsigned char* mbase = mask + (size_t)b * N_TOK * N_TOK;

    for (int m0 = 0; m0 < N_TOK; m0 += 64) {
        __syncthreads();   // prior PV done before overwriting Ks/Vs
        for (int i = tid; i < 4096; i += 256) {
            int r = i >> 6, c = i & 63;
            size_t base = (size_t)(b * N_TOK + m0 + r) * C3 + h * 64 + c;
            Ks[c * 65 + r] = qkv[base + 512];
            Vs[r * 64 + c] = qkv[base + 1024];
        }
        if (tid < 64) {
            kcx[tid] = coords[(size_t)(b * N_TOK + m0 + tid) * 2];
            kcy[tid] = coords[(size_t)(b * N_TOK + m0 + tid) * 2 + 1];
        }
        __syncthreads();

        // S = Q @ K^T (4x4 per thread)
        float S[4][4];
        #pragma unroll
        for (int i = 0; i < 4; i++)
            #pragma unroll
            for (int j = 0; j < 4; j++) S[i][j] = 0.0f;
        #pragma unroll 8
        for (int kk = 0; kk < 64; kk++) {
            float a[4], bb[4];
            #pragma unroll
            for (int i = 0; i < 4; i++) a[i] = Qs[kk * 65 + ty * 4 + i];
            #pragma unroll
            for (int j = 0; j < 4; j++) bb[j] = Ks[kk * 65 + tx * 4 + j];
            #pragma unroll
            for (int i = 0; i < 4; i++)
                #pragma unroll
                for (int j = 0; j < 4; j++) S[i][j] = fmaf(a[i], bb[j], S[i][j]);
        }

        // + distance bias, mask
        #pragma unroll
        for (int j = 0; j < 4; j++) {
            int mm = m0 + tx * 4 + j;
            float kx = kcx[tx * 4 + j], ky = kcy[tx * 4 + j];
            #pragma unroll
            for (int i = 0; i < 4; i++) {
                float dx = qx[i] - kx, dy = qy[i] - ky;
                float v = S[i][j] + sqrtf(dx * dx + dy * dy) * we;
                if (mbase[(size_t)(n0 + ty * 4 + i) * N_TOK + mm]) v = -1e9f;
                S[i][j] = v;
            }
        }

        // online softmax (row groups = 16 consecutive lanes)
        #pragma unroll
        for (int i = 0; i < 4; i++) {
            float mx = fmaxf(fmaxf(S[i][0], S[i][1]), fmaxf(S[i][2], S[i][3]));
            #pragma unroll
            for (int o = 8; o; o >>= 1) mx = fmaxf(mx, __shfl_xor_sync(0xffffffffu, mx, o, 16));
            float mnew = fmaxf(mrun[i], mx);
            float corr = __expf(mrun[i] - mnew);
            float ls = 0.0f;
            #pragma unroll
            for (int j = 0; j < 4; j++) { S[i][j] = __expf(S[i][j] - mnew); ls += S[i][j]; }
            #pragma unroll
            for (int o = 8; o; o >>= 1) ls += __shfl_xor_sync(0xffffffffu, ls, o, 16);
            lrun[i] = lrun[i] * corr + ls;
            mrun[i] = mnew;
            #pragma unroll
            for (int j = 0; j < 4; j++) O[i][j] *= corr;
        }

        __syncthreads();   // everyone done reading Ks
        #pragma unroll
        for (int i = 0; i < 4; i++)
            #pragma unroll
            for (int j = 0; j < 4; j++) Ks[(ty * 4 + i) * 65 + tx * 4 + j] = S[i][j];
        __syncthreads();

        // O += P @ V
        #pragma unroll 8
        for (int kk = 0; kk < 64; kk++) {
            float p[4];
            #pragma unroll
            for (int i = 0; i < 4; i++) p[i] = Ks[(ty * 4 + i) * 65 + kk];
            float4 vv = *(const float4*)(Vs + kk * 64 + tx * 4);
            #pragma unroll
            for (int i = 0; i < 4; i++) {
                O[i][0] = fmaf(p[i], vv.x, O[i][0]);
                O[i][1] = fmaf(p[i], vv.y, O[i][1]);
                O[i][2] = fmaf(p[i], vv.z, O[i][2]);
                O[i][3] = fmaf(p[i], vv.w, O[i][3]);
            }
        }
    }

    #pragma unroll
    for (int i = 0; i < 4; i++) {
        float inv = 1.0f / lrun[i];
        size_t row = (size_t)(b * N_TOK + n0 + ty * 4 + i) * D_MODEL + h * 64 + tx * 4;
        #pragma unroll
        for (int j = 0; j < 4; j++) out[row + j] = O[i][j] * inv;
    }
}

// ---------------- launch ---------------------------------------------------------
extern "C" void kernel_launch(void* const* d_in, const int* in_sizes, int n_in,
                              void* d_out, int out_size) {
    const float* x      = (const float*)d_in[0];   // token_embs (B,N,512)
    const float* coords = (const float*)d_in[1];   // (B,N,2)
    const unsigned char* mask = (const unsigned char*)d_in[2];  // (B,N,N) bool
    const float* ln1g = (const float*)d_in[3];
    const float* ln1b = (const float*)d_in[4];
    const float* wqkv = (const float*)d_in[5];
    const float* bqkv = (const float*)d_in[6];
    const float* wedge= (const float*)d_in[7];
    const float* wout = (const float*)d_in[8];
    const float* bout = (const float*)d_in[9];
    const float* ln2g = (const float*)d_in[10];
    const float* ln2b = (const float*)d_in[11];
    const float* w1   = (const float*)d_in[12];
    const float* b1   = (const float*)d_in[13];
    const float* w2   = (const float*)d_in[14];
    const float* b2   = (const float*)d_in[15];
    float* out = (float*)d_out;

    void *p;
    float *xln, *qkv, *att, *x2, *hid;
    cudaGetSymbolAddress(&p, g_xln); xln = (float*)p;
    cudaGetSymbolAddress(&p, g_qkv); qkv = (float*)p;
    cudaGetSymbolAddress(&p, g_att); att = (float*)p;
    cudaGetSymbolAddress(&p, g_x2);  x2  = (float*)p;
    cudaGetSymbolAddress(&p, g_hid); hid = (float*)p;

    const int ATTN_SMEM = (64 * 65 * 2 + 64 * 64 + 128) * 4;  // 50176 B
    cudaFuncSetAttribute(attn_kernel, cudaFuncAttributeMaxDynamicSharedMemorySize, ATTN_SMEM);

    // 1) LN1
    ln_kernel<<<M_ROWS, 256>>>(x, ln1g, ln1b, xln);
    // 2) QKV: (2048,512)@(512,1536)
    gemm_kernel<<<dim3(3 * D_MODEL / 64, M_ROWS / 128), 256>>>(xln, wqkv, bqkv, nullptr, qkv,
                                                               M_ROWS, 3 * D_MODEL, D_MODEL, 0);
    // 3) attention
    attn_kernel<<<dim3(N_TOK / 64, HEADS, BATCH), 256, ATTN_SMEM>>>(qkv, coords, mask, wedge, att);
    // 4) out proj + residual(token_embs)
    gemm_kernel<<<dim3(D_MODEL / 64, M_ROWS / 128), 256>>>(att, wout, bout, x, x2,
                                                           M_ROWS, D_MODEL, D_MODEL, 0);
    // 5) LN2
    ln_kernel<<<M_ROWS, 256>>>(x2, ln2g, ln2b, xln);
    // 6) fc1 + gelu
    gemm_kernel<<<dim3(HIDDEN / 64, M_ROWS / 128), 256>>>(xln, w1, b1, nullptr, hid,
                                                          M_ROWS, HIDDEN, D_MODEL, 1);
    // 7) fc2 + residual(x2) -> out
    gemm_kernel<<<dim3(D_MODEL / 64, M_ROWS / 128), 256>>>(hid, w2, b2, x2, out,
                                                           M_ROWS, D_MODEL, HIDDEN, 0);
}

// round 2
// speedup vs baseline: 1.8837x; 1.8837x over previous
#include <cuda_runtime.h>
#include <math.h>
#include <stdint.h>

#define D_MODEL 512
#define N_TOK   1024
#define BATCH   2
#define HEADS   8
#define HIDDEN  2048
#define M_ROWS  (BATCH * N_TOK)   // 2048

// ---------------- scratch (static device globals; no allocation) ----------------
__device__ __align__(256) float g_xln[M_ROWS * D_MODEL];
__device__ __align__(256) float g_qkv[M_ROWS * 3 * D_MODEL];
__device__ __align__(256) float g_att[M_ROWS * D_MODEL];
__device__ __align__(256) float g_x2 [M_ROWS * D_MODEL];
__device__ __align__(256) float g_hid[M_ROWS * HIDDEN];

// ---------------- helpers --------------------------------------------------------
__device__ __forceinline__ void cp16(uint32_t smem, const void* g) {
    asm volatile("cp.async.cg.shared.global [%0], [%1], 16;" :: "r"(smem), "l"(g));
}
__device__ __forceinline__ void cp_commit() { asm volatile("cp.async.commit_group;"); }
template<int N> __device__ __forceinline__ void cp_wait() {
    asm volatile("cp.async.wait_group %0;" :: "n"(N));
}
__device__ __forceinline__ uint32_t f2tf(float x) {
    uint32_t r; asm("cvt.rna.tf32.f32 %0, %1;" : "=r"(r) : "f"(x)); return r;
}
__device__ __forceinline__ void mma_tf32(float c[4], const uint32_t a[4], const uint32_t b[2]) {
    asm volatile(
        "mma.sync.aligned.m16n8k8.row.col.f32.tf32.tf32.f32 "
        "{%0,%1,%2,%3}, {%4,%5,%6,%7}, {%8,%9}, {%0,%1,%2,%3};"
        : "+f"(c[0]), "+f"(c[1]), "+f"(c[2]), "+f"(c[3])
        : "r"(a[0]), "r"(a[1]), "r"(a[2]), "r"(a[3]), "r"(b[0]), "r"(b[1]));
}

// ---------------- LayerNorm ------------------------------------------------------
__global__ void ln_kernel(const float* __restrict__ x, const float* __restrict__ g,
                          const float* __restrict__ b, float* __restrict__ y) {
    int row = blockIdx.x;
    const float* xr = x + (size_t)row * D_MODEL;
    int t = threadIdx.x;
    float v0 = xr[t];
    float v1 = xr[t + 256];

    __shared__ float sh[8], sh2[8];
    int w = t >> 5, lane = t & 31;

    float s = v0 + v1;
    #pragma unroll
    for (int o = 16; o; o >>= 1) s += __shfl_xor_sync(0xffffffffu, s, o);
    if (lane == 0) sh[w] = s;
    __syncthreads();
    float mean = (sh[0]+sh[1]+sh[2]+sh[3]+sh[4]+sh[5]+sh[6]+sh[7]) * (1.0f / D_MODEL);

    float d0 = v0 - mean, d1 = v1 - mean;
    float q = d0 * d0 + d1 * d1;
    #pragma unroll
    for (int o = 16; o; o >>= 1) q += __shfl_xor_sync(0xffffffffu, q, o);
    if (lane == 0) sh2[w] = q;
    __syncthreads();
    float var = (sh2[0]+sh2[1]+sh2[2]+sh2[3]+sh2[4]+sh2[5]+sh2[6]+sh2[7]) * (1.0f / D_MODEL);
    float inv = rsqrtf(var + 1e-5f);

    float* yr = y + (size_t)row * D_MODEL;
    yr[t]       = d0 * inv * g[t]       + b[t];
    yr[t + 256] = d1 * inv * g[t + 256] + b[t + 256];
}

// ---------------- tf32 tensor-core GEMM ------------------------------------------
// C[M,N] = A[M,K] @ B[K,N] + bias (+gelu) (+res). BM=128, BK=32, double-buffered
// cp.async, XOR-swizzled smem (bank-conflict-free for stores and mma frag loads).
template<int BN, int WARPS_M, int WARPS_N>
__global__ void __launch_bounds__(256) gemm_tf32(
        const float* __restrict__ A, const float* __restrict__ B,
        const float* __restrict__ bias, const float* __restrict__ res,
        float* __restrict__ C, int M, int Nn, int K, int do_gelu) {
    constexpr int BM = 128, BK = 32;
    constexpr int WM = BM / WARPS_M;       // 64 or 32
    constexpr int WN = BN / WARPS_N;       // 32
    constexpr int MT = WM / 16;            // 4 or 2
    constexpr int NT = WN / 8;             // 4

    extern __shared__ float sm[];
    float* As = sm;                        // [2][BM][BK]
    float* Bs = sm + 2 * BM * BK;          // [2][BK][BN]

    const int tid  = threadIdx.x;
    const int warp = tid >> 5;
    const int lane = tid & 31;
    const int gpid = lane >> 2;            // group id (0..7)
    const int tgid = lane & 3;             // thread-in-group (0..3)
    const int wm = warp / WARPS_N;
    const int wn = warp % WARPS_N;
    const int m0 = blockIdx.y * BM;
    const int n0 = blockIdx.x * BN;

    const uint32_t s_as = (uint32_t)__cvta_generic_to_shared(As);
    const uint32_t s_bs = (uint32_t)__cvta_generic_to_shared(Bs);

    float acc[MT][NT][4];
    #pragma unroll
    for (int i = 0; i < MT; i++)
        #pragma unroll
        for (int j = 0; j < NT; j++)
            #pragma unroll
            for (int e = 0; e < 4; e++) acc[i][j][e] = 0.0f;

    auto loadA = [&](int buf, int k0) {
        #pragma unroll
        for (int u = 0; u < 4; u++) {
            int row = (tid >> 3) + u * 32;
            int g   = tid & 7;
            const float* src = A + (size_t)(m0 + row) * K + k0 + g * 4;
            uint32_t dst = s_as + (uint32_t)((buf * BM * BK + row * BK +
                                             ((g ^ (row & 7)) * 4)) * 4);
            cp16(dst, src);
        }
    };
    auto loadB = [&](int buf, int k0) {
        constexpr int CPR = BN / 4;        // 16B chunks per row
        constexpr int RPP = 256 / CPR;     // rows per pass
        #pragma unroll
        for (int u = 0; u < BK / RPP; u++) {
            int row = tid / CPR + u * RPP;
            int g   = tid % CPR;
            const float* src = B + (size_t)(k0 + row) * Nn + n0 + g * 4;
            uint32_t dst = s_bs + (uint32_t)((buf * BK * BN + row * BN +
                                             ((g ^ ((row & 3) << 1)) * 4)) * 4);
            cp16(dst, src);
        }
    };

    const int tiles = K >> 5;
    loadA(0, 0); loadB(0, 0); cp_commit();

    for (int kt = 0; kt < tiles; kt++) {
        const int cbuf = kt & 1;
        if (kt + 1 < tiles) {
            loadA(cbuf ^ 1, (kt + 1) * BK);
            loadB(cbuf ^ 1, (kt + 1) * BK);
            cp_commit();
            cp_wait<1>();
        } else {
            cp_wait<0>();
        }
        __syncthreads();

        const float* as = As + cbuf * BM * BK;
        const float* bs = Bs + cbuf * BK * BN;

        #pragma unroll
        for (int ks = 0; ks < 4; ks++) {
            const int k = ks * 8;
            uint32_t af[MT][4];
            #pragma unroll
            for (int mt = 0; mt < MT; mt++) {
                int r  = wm * WM + mt * 16 + gpid;
                int c  = k + tgid;
                int sw = (r & 7) << 2;
                af[mt][0] = f2tf(as[r * BK + (c ^ sw)]);
                af[mt][1] = f2tf(as[(r + 8) * BK + (c ^ sw)]);
                af[mt][2] = f2tf(as[r * BK + ((c + 4) ^ sw)]);
                af[mt][3] = f2tf(as[(r + 8) * BK + ((c + 4) ^ sw)]);
            }
            uint32_t bf[NT][2];
            #pragma unroll
            for (int nt = 0; nt < NT; nt++) {
                int n  = wn * WN + nt * 8 + gpid;
                int kk = k + tgid;
                int sw = (kk & 3) << 3;
                bf[nt][0] = f2tf(bs[kk * BN + (n ^ sw)]);
                bf[nt][1] = f2tf(bs[(kk + 4) * BN + (n ^ sw)]);
            }
            #pragma unroll
            for (int mt = 0; mt < MT; mt++)
                #pragma unroll
                for (int nt = 0; nt < NT; nt++)
                    mma_tf32(acc[mt][nt], af[mt], bf[nt]);
        }
        __syncthreads();
    }

    // epilogue
    #pragma unroll
    for (int mt = 0; mt < MT; mt++) {
        #pragma unroll
        for (int nt = 0; nt < NT; nt++) {
            int r0 = m0 + wm * WM + mt * 16 + gpid;
            int c0 = n0 + wn * WN + nt * 8 + 2 * tgid;
            float bb0 = bias[c0], bb1 = bias[c0 + 1];
            float v00 = acc[mt][nt][0] + bb0, v01 = acc[mt][nt][1] + bb1;
            float v10 = acc[mt][nt][2] + bb0, v11 = acc[mt][nt][3] + bb1;
            if (do_gelu) {
                v00 = 0.5f * v00 * (1.0f + erff(v00 * 0.70710678118654752f));
                v01 = 0.5f * v01 * (1.0f + erff(v01 * 0.70710678118654752f));
                v10 = 0.5f * v10 * (1.0f + erff(v10 * 0.70710678118654752f));
                v11 = 0.5f * v11 * (1.0f + erff(v11 * 0.70710678118654752f));
            }
            if (res) {
                v00 += res[(size_t)r0 * Nn + c0];
                v01 += res[(size_t)r0 * Nn + c0 + 1];
                v10 += res[(size_t)(r0 + 8) * Nn + c0];
                v11 += res[(size_t)(r0 + 8) * Nn + c0 + 1];
            }
            *(float2*)(C + (size_t)r0 * Nn + c0)       = make_float2(v00, v01);
            *(float2*)(C + (size_t)(r0 + 8) * Nn + c0) = make_float2(v10, v11);
        }
    }
}

// ---------------- Flash attention with distance bias ---------------------------
// bias[b,h,n,m] = ||coords[b,n]-coords[b,m]|| * w_edge[2,h]  (frame average collapses)
__global__ void attn_kernel(const float* __restrict__ qkv, const float* __restrict__ coords,
                            const unsigned char* __restrict__ mask,
                            const float* __restrict__ w_edge, float* __restrict__ out) {
    extern __shared__ float sm[];
    float* Qs  = sm;                 // [64 d][65 q]
    float* Ks  = sm + 64 * 65;       // [64 d][65 k]; reused as Ps
    float* Vs  = Ks + 64 * 65;       // [64 k][64 d]
    float* kcx = Vs + 64 * 64;
    float* kcy = kcx + 64;

    int b = blockIdx.z, h = blockIdx.y;
    int n0 = blockIdx.x * 64;
    int tid = threadIdx.x, tx = tid & 15, ty = tid >> 4;
    const float we = w_edge[2 * HEADS + h];
    const float scale = 0.125f;
    const int C3 = 3 * D_MODEL;

    for (int i = tid; i < 4096; i += 256) {
        int r = i >> 6, c = i & 63;
        Qs[c * 65 + r] = qkv[(size_t)(b * N_TOK + n0 + r) * C3 + h * 64 + c] * scale;
    }
    float qx[4], qy[4];
    #pragma unroll
    for (int i = 0; i < 4; i++) {
        int n = n0 + ty * 4 + i;
        qx[i] = coords[(size_t)(b * N_TOK + n) * 2];
        qy[i] = coords[(size_t)(b * N_TOK + n) * 2 + 1];
    }

    float mrun[4], lrun[4], O[4][4];
    #pragma unroll
    for (int i = 0; i < 4; i++) {
        mrun[i] = -3.0e38f; lrun[i] = 0.0f;
        #pragma unroll
        for (int j = 0; j < 4; j++) O[i][j] = 0.0f;
    }

    const unsigned char* mbase = mask + (size_t)b * N_TOK * N_TOK;

    for (int m0 = 0; m0 < N_TOK; m0 += 64) {
        __syncthreads();
        for (int i = tid; i < 4096; i += 256) {
            int r = i >> 6, c = i & 63;
            size_t base = (size_t)(b * N_TOK + m0 + r) * C3 + h * 64 + c;
            Ks[c * 65 + r] = qkv[base + 512];
            Vs[r * 64 + c] = qkv[base + 1024];
        }
        if (tid < 64) {
            kcx[tid] = coords[(size_t)(b * N_TOK + m0 + tid) * 2];
            kcy[tid] = coords[(size_t)(b * N_TOK + m0 + tid) * 2 + 1];
        }
        __syncthreads();

        float S[4][4];
        #pragma unroll
        for (int i = 0; i < 4; i++)
            #pragma unroll
            for (int j = 0; j < 4; j++) S[i][j] = 0.0f;
        #pragma unroll 8
        for (int kk = 0; kk < 64; kk++) {
            float a[4], bb[4];
            #pragma unroll
            for (int i = 0; i < 4; i++) a[i] = Qs[kk * 65 + ty * 4 + i];
            #pragma unroll
            for (int j = 0; j < 4; j++) bb[j] = Ks[kk * 65 + tx * 4 + j];
            #pragma unroll
            for (int i = 0; i < 4; i++)
                #pragma unroll
                for (int j = 0; j < 4; j++) S[i][j] = fmaf(a[i], bb[j], S[i][j]);
        }

        #pragma unroll
        for (int j = 0; j < 4; j++) {
            int mm = m0 + tx * 4 + j;
            float kx = kcx[tx * 4 + j], ky = kcy[tx * 4 + j];
            #pragma unroll
            for (int i = 0; i < 4; i++) {
                float dx = qx[i] - kx, dy = qy[i] - ky;
                float v = S[i][j] + sqrtf(dx * dx + dy * dy) * we;
                if (mbase[(size_t)(n0 + ty * 4 + i) * N_TOK + mm]) v = -1e9f;
                S[i][j] = v;
            }
        }

        #pragma unroll
        for (int i = 0; i < 4; i++) {
            float mx = fmaxf(fmaxf(S[i][0], S[i][1]), fmaxf(S[i][2], S[i][3]));
            #pragma unroll
            for (int o = 8; o; o >>= 1) mx = fmaxf(mx, __shfl_xor_sync(0xffffffffu, mx, o, 16));
            float mnew = fmaxf(mrun[i], mx);
            float corr = __expf(mrun[i] - mnew);
            float ls = 0.0f;
            #pragma unroll
            for (int j = 0; j < 4; j++) { S[i][j] = __expf(S[i][j] - mnew); ls += S[i][j]; }
            #pragma unroll
            for (int o = 8; o; o >>= 1) ls += __shfl_xor_sync(0xffffffffu, ls, o, 16);
            lrun[i] = lrun[i] * corr + ls;
            mrun[i] = mnew;
            #pragma unroll
            for (int j = 0; j < 4; j++) O[i][j] *= corr;
        }

        __syncthreads();
        #pragma unroll
        for (int i = 0; i < 4; i++)
            #pragma unroll
            for (int j = 0; j < 4; j++) Ks[(ty * 4 + i) * 65 + tx * 4 + j] = S[i][j];
        __syncthreads();

        #pragma unroll 8
        for (int kk = 0; kk < 64; kk++) {
            float p[4];
            #pragma unroll
            for (int i = 0; i < 4; i++) p[i] = Ks[(ty * 4 + i) * 65 + kk];
            float4 vv = *(const float4*)(Vs + kk * 64 + tx * 4);
            #pragma unroll
            for (int i = 0; i < 4; i++) {
                O[i][0] = fmaf(p[i], vv.x, O[i][0]);
                O[i][1] = fmaf(p[i], vv.y, O[i][1]);
                O[i][2] = fmaf(p[i], vv.z, O[i][2]);
                O[i][3] = fmaf(p[i], vv.w, O[i][3]);
            }
        }
    }

    #pragma unroll
    for (int i = 0; i < 4; i++) {
        float inv = 1.0f / lrun[i];
        size_t row = (size_t)(b * N_TOK + n0 + ty * 4 + i) * D_MODEL + h * 64 + tx * 4;
        #pragma unroll
        for (int j = 0; j < 4; j++) out[row + j] = O[i][j] * inv;
    }
}

// ---------------- launch ---------------------------------------------------------
extern "C" void kernel_launch(void* const* d_in, const int* in_sizes, int n_in,
                              void* d_out, int out_size) {
    const float* x      = (const float*)d_in[0];
    const float* coords = (const float*)d_in[1];
    const unsigned char* mask = (const unsigned char*)d_in[2];
    const float* ln1g = (const float*)d_in[3];
    const float* ln1b = (const float*)d_in[4];
    const float* wqkv = (const float*)d_in[5];
    const float* bqkv = (const float*)d_in[6];
    const float* wedge= (const float*)d_in[7];
    const float* wout = (const float*)d_in[8];
    const float* bout = (const float*)d_in[9];
    const float* ln2g = (const float*)d_in[10];
    const float* ln2b = (const float*)d_in[11];
    const float* w1   = (const float*)d_in[12];
    const float* b1   = (const float*)d_in[13];
    const float* w2   = (const float*)d_in[14];
    const float* b2   = (const float*)d_in[15];
    float* out = (float*)d_out;

    void *p;
    float *xln, *qkv, *att, *x2, *hid;
    cudaGetSymbolAddress(&p, g_xln); xln = (float*)p;
    cudaGetSymbolAddress(&p, g_qkv); qkv = (float*)p;
    cudaGetSymbolAddress(&p, g_att); att = (float*)p;
    cudaGetSymbolAddress(&p, g_x2);  x2  = (float*)p;
    cudaGetSymbolAddress(&p, g_hid); hid = (float*)p;

    const int ATTN_SMEM  = (64 * 65 * 2 + 64 * 64 + 128) * 4;  // 50176 B
    const int GEMM_SMEM_A = 2 * (128 * 32 + 32 * 128) * 4;     // 65536 B
    const int GEMM_SMEM_B = 2 * (128 * 32 + 32 * 64) * 4;      // 49152 B
    cudaFuncSetAttribute(attn_kernel, cudaFuncAttributeMaxDynamicSharedMemorySize, ATTN_SMEM);
    cudaFuncSetAttribute(gemm_tf32<128,2,4>, cudaFuncAttributeMaxDynamicSharedMemorySize, GEMM_SMEM_A);
    cudaFuncSetAttribute(gemm_tf32<64,4,2>,  cudaFuncAttributeMaxDynamicSharedMemorySize, GEMM_SMEM_B);

    // 1) LN1
    ln_kernel<<<M_ROWS, 256>>>(x, ln1g, ln1b, xln);
    // 2) QKV: (2048,1536,512)
    gemm_tf32<128,2,4><<<dim3(1536/128, M_ROWS/128), 256, GEMM_SMEM_A>>>(
        xln, wqkv, bqkv, nullptr, qkv, M_ROWS, 1536, D_MODEL, 0);
    // 3) attention
    attn_kernel<<<dim3(N_TOK/64, HEADS, BATCH), 256, ATTN_SMEM>>>(qkv, coords, mask, wedge, att);
    // 4) out proj + residual(token_embs)
    gemm_tf32<64,4,2><<<dim3(512/64, M_ROWS/128), 256, GEMM_SMEM_B>>>(
        att, wout, bout, x, x2, M_ROWS, D_MODEL, D_MODEL, 0);
    // 5) LN2
    ln_kernel<<<M_ROWS, 256>>>(x2, ln2g, ln2b, xln);
    // 6) fc1 + gelu
    gemm_tf32<128,2,4><<<dim3(HIDDEN/128, M_ROWS/128), 256, GEMM_SMEM_A>>>(
        xln, w1, b1, nullptr, hid, M_ROWS, HIDDEN, D_MODEL, 1);
    // 7) fc2 + residual(x2) -> out
    gemm_tf32<64,4,2><<<dim3(512/64, M_ROWS/128), 256, GEMM_SMEM_B>>>(
        hid, w2, b2, x2, out, M_ROWS, D_MODEL, HIDDEN, 0);
}

// round 3
// speedup vs baseline: 2.6553x; 1.4096x over previous
#include <cuda_runtime.h>
#include <math.h>
#include <stdint.h>

#define D_MODEL 512
#define N_TOK   1024
#define BATCH   2
#define HEADS   8
#define HIDDEN  2048
#define M_ROWS  (BATCH * N_TOK)   // 2048

// ---------------- scratch (static device globals; no allocation) ----------------
__device__ __align__(256) float g_xln[M_ROWS * D_MODEL];
__device__ __align__(256) float g_qkv[M_ROWS * 3 * D_MODEL];
__device__ __align__(256) float g_att[M_ROWS * D_MODEL];
__device__ __align__(256) float g_x2 [M_ROWS * D_MODEL];
__device__ __align__(256) float g_hid[M_ROWS * HIDDEN];

// ---------------- helpers --------------------------------------------------------
__device__ __forceinline__ void cp16(uint32_t smem, const void* g) {
    asm volatile("cp.async.cg.shared.global [%0], [%1], 16;" :: "r"(smem), "l"(g));
}
__device__ __forceinline__ void cp_commit() { asm volatile("cp.async.commit_group;"); }
template<int N> __device__ __forceinline__ void cp_wait() {
    asm volatile("cp.async.wait_group %0;" :: "n"(N));
}
__device__ __forceinline__ uint32_t f2tf(float x) {
    uint32_t r; asm("cvt.rna.tf32.f32 %0, %1;" : "=r"(r) : "f"(x)); return r;
}
__device__ __forceinline__ void mma_tf32(float c[4], const uint32_t a[4], const uint32_t b[2]) {
    asm volatile(
        "mma.sync.aligned.m16n8k8.row.col.f32.tf32.tf32.f32 "
        "{%0,%1,%2,%3}, {%4,%5,%6,%7}, {%8,%9}, {%0,%1,%2,%3};"
        : "+f"(c[0]), "+f"(c[1]), "+f"(c[2]), "+f"(c[3])
        : "r"(a[0]), "r"(a[1]), "r"(a[2]), "r"(a[3]), "r"(b[0]), "r"(b[1]));
}

// ---------------- LayerNorm ------------------------------------------------------
__global__ void ln_kernel(const float* __restrict__ x, const float* __restrict__ g,
                          const float* __restrict__ b, float* __restrict__ y) {
    int row = blockIdx.x;
    const float* xr = x + (size_t)row * D_MODEL;
    int t = threadIdx.x;
    float v0 = xr[t];
    float v1 = xr[t + 256];

    __shared__ float sh[8], sh2[8];
    int w = t >> 5, lane = t & 31;

    float s = v0 + v1;
    #pragma unroll
    for (int o = 16; o; o >>= 1) s += __shfl_xor_sync(0xffffffffu, s, o);
    if (lane == 0) sh[w] = s;
    __syncthreads();
    float mean = (sh[0]+sh[1]+sh[2]+sh[3]+sh[4]+sh[5]+sh[6]+sh[7]) * (1.0f / D_MODEL);

    float d0 = v0 - mean, d1 = v1 - mean;
    float q = d0 * d0 + d1 * d1;
    #pragma unroll
    for (int o = 16; o; o >>= 1) q += __shfl_xor_sync(0xffffffffu, q, o);
    if (lane == 0) sh2[w] = q;
    __syncthreads();
    float var = (sh2[0]+sh2[1]+sh2[2]+sh2[3]+sh2[4]+sh2[5]+sh2[6]+sh2[7]) * (1.0f / D_MODEL);
    float inv = rsqrtf(var + 1e-5f);

    float* yr = y + (size_t)row * D_MODEL;
    yr[t]       = d0 * inv * g[t]       + b[t];
    yr[t + 256] = d1 * inv * g[t + 256] + b[t + 256];
}

// ---------------- tf32 tensor-core GEMM ------------------------------------------
template<int BM, int BN, int WARPS_M, int WARPS_N, int THREADS>
__global__ void __launch_bounds__(THREADS) gemm_tf32(
        const float* __restrict__ A, const float* __restrict__ B,
        const float* __restrict__ bias, const float* __restrict__ res,
        float* __restrict__ C, int M, int Nn, int K, int do_gelu) {
    constexpr int BK = 32;
    constexpr int WM = BM / WARPS_M;
    constexpr int WN = BN / WARPS_N;
    constexpr int MT = WM / 16;
    constexpr int NT = WN / 8;

    extern __shared__ float sm[];
    float* As = sm;                        // [2][BM][BK]
    float* Bs = sm + 2 * BM * BK;          // [2][BK][BN]

    const int tid  = threadIdx.x;
    const int warp = tid >> 5;
    const int lane = tid & 31;
    const int gpid = lane >> 2;
    const int tgid = lane & 3;
    const int wm = warp / WARPS_N;
    const int wn = warp % WARPS_N;
    const int m0 = blockIdx.y * BM;
    const int n0 = blockIdx.x * BN;

    const uint32_t s_as = (uint32_t)__cvta_generic_to_shared(As);
    const uint32_t s_bs = (uint32_t)__cvta_generic_to_shared(Bs);

    float acc[MT][NT][4];
    #pragma unroll
    for (int i = 0; i < MT; i++)
        #pragma unroll
        for (int j = 0; j < NT; j++)
            #pragma unroll
            for (int e = 0; e < 4; e++) acc[i][j][e] = 0.0f;

    auto loadA = [&](int buf, int k0) {
        constexpr int RA = THREADS / 8;
        #pragma unroll
        for (int u = 0; u < BM / RA; u++) {
            int row = (tid >> 3) + u * RA;
            int g   = tid & 7;
            const float* src = A + (size_t)(m0 + row) * K + k0 + g * 4;
            uint32_t dst = s_as + (uint32_t)((buf * BM * BK + row * BK +
                                             ((g ^ (row & 7)) * 4)) * 4);
            cp16(dst, src);
        }
    };
    auto loadB = [&](int buf, int k0) {
        constexpr int CPR = BN / 4;
        constexpr int RPP = THREADS / CPR;
        #pragma unroll
        for (int u = 0; u < BK / RPP; u++) {
            int row = tid / CPR + u * RPP;
            int g   = tid % CPR;
            const float* src = B + (size_t)(k0 + row) * Nn + n0 + g * 4;
            uint32_t dst = s_bs + (uint32_t)((buf * BK * BN + row * BN +
                                             ((g ^ ((row & 3) << 1)) * 4)) * 4);
            cp16(dst, src);
        }
    };

    const int tiles = K >> 5;
    loadA(0, 0); loadB(0, 0); cp_commit();

    for (int kt = 0; kt < tiles; kt++) {
        const int cbuf = kt & 1;
        if (kt + 1 < tiles) {
            loadA(cbuf ^ 1, (kt + 1) * BK);
            loadB(cbuf ^ 1, (kt + 1) * BK);
            cp_commit();
            cp_wait<1>();
        } else {
            cp_wait<0>();
        }
        __syncthreads();

        const float* as = As + cbuf * BM * BK;
        const float* bs = Bs + cbuf * BK * BN;

        #pragma unroll
        for (int ks = 0; ks < 4; ks++) {
            const int k = ks * 8;
            uint32_t af[MT][4];
            #pragma unroll
            for (int mt = 0; mt < MT; mt++) {
                int r  = wm * WM + mt * 16 + gpid;
                int c  = k + tgid;
                int sw = (r & 7) << 2;
                af[mt][0] = f2tf(as[r * BK + (c ^ sw)]);
                af[mt][1] = f2tf(as[(r + 8) * BK + (c ^ sw)]);
                af[mt][2] = f2tf(as[r * BK + ((c + 4) ^ sw)]);
                af[mt][3] = f2tf(as[(r + 8) * BK + ((c + 4) ^ sw)]);
            }
            uint32_t bf[NT][2];
            #pragma unroll
            for (int nt = 0; nt < NT; nt++) {
                int n  = wn * WN + nt * 8 + gpid;
                int kk = k + tgid;
                int sw = (kk & 3) << 3;
                bf[nt][0] = f2tf(bs[kk * BN + (n ^ sw)]);
                bf[nt][1] = f2tf(bs[(kk + 4) * BN + (n ^ sw)]);
            }
            #pragma unroll
            for (int mt = 0; mt < MT; mt++)
                #pragma unroll
                for (int nt = 0; nt < NT; nt++)
                    mma_tf32(acc[mt][nt], af[mt], bf[nt]);
        }
        __syncthreads();
    }

    #pragma unroll
    for (int mt = 0; mt < MT; mt++) {
        #pragma unroll
        for (int nt = 0; nt < NT; nt++) {
            int r0 = m0 + wm * WM + mt * 16 + gpid;
            int c0 = n0 + wn * WN + nt * 8 + 2 * tgid;
            float bb0 = bias[c0], bb1 = bias[c0 + 1];
            float v00 = acc[mt][nt][0] + bb0, v01 = acc[mt][nt][1] + bb1;
            float v10 = acc[mt][nt][2] + bb0, v11 = acc[mt][nt][3] + bb1;
            if (do_gelu) {
                v00 = 0.5f * v00 * (1.0f + erff(v00 * 0.70710678118654752f));
                v01 = 0.5f * v01 * (1.0f + erff(v01 * 0.70710678118654752f));
                v10 = 0.5f * v10 * (1.0f + erff(v10 * 0.70710678118654752f));
                v11 = 0.5f * v11 * (1.0f + erff(v11 * 0.70710678118654752f));
            }
            if (res) {
                v00 += res[(size_t)r0 * Nn + c0];
                v01 += res[(size_t)r0 * Nn + c0 + 1];
                v10 += res[(size_t)(r0 + 8) * Nn + c0];
                v11 += res[(size_t)(r0 + 8) * Nn + c0 + 1];
            }
            *(float2*)(C + (size_t)r0 * Nn + c0)       = make_float2(v00, v01);
            *(float2*)(C + (size_t)(r0 + 8) * Nn + c0) = make_float2(v10, v11);
        }
    }
}

// ---------------- tf32 mma flash attention with distance bias --------------------
// bias[b,h,n,m] = ||coords[b,n]-coords[b,m]|| * w_edge[2,h]  (frame average collapses)
// 128 threads = 4 warps, each warp: 16 queries x 64 keys, d=64. Double-buffered
// cp.async K/V/mask/coords. Q fragments live in registers for the whole kernel.
__global__ void __launch_bounds__(128) attn_mma(
        const float* __restrict__ qkv, const float* __restrict__ coords,
        const unsigned char* __restrict__ mask, const float* __restrict__ w_edge,
        float* __restrict__ out) {
    extern __shared__ float sm[];
    float* Ks = sm;                    // [2][64*64] swizzled c^( (r&7)<<2 )
    float* Vs = Ks + 2 * 4096;         // [2][64*64] swizzled c^( (r&3)<<3 )
    float* Ps = Vs + 2 * 4096;         // [64*64]  Q staging, then per-warp P
    float* kc = Ps + 4096;             // [2][128] key coords
    unsigned char* Ms = (unsigned char*)(kc + 256);  // [2][4096] mask tile

    const int b = blockIdx.z, h = blockIdx.y, n0 = blockIdx.x * 64;
    const int tid = threadIdx.x, warp = tid >> 5, lane = tid & 31;
    const int g = lane >> 2, t = lane & 3;
    const float we = w_edge[2 * HEADS + h];

    const uint32_t s_ks = (uint32_t)__cvta_generic_to_shared(Ks);
    const uint32_t s_vs = (uint32_t)__cvta_generic_to_shared(Vs);
    const uint32_t s_kc = (uint32_t)__cvta_generic_to_shared(kc);
    const uint32_t s_ms = (uint32_t)__cvta_generic_to_shared(Ms);

    auto issue = [&](int buf, int m0) {
        #pragma unroll
        for (int u = 0; u < 8; u++) {
            int f = tid + u * 128; int r = f >> 4; int cc = (f & 15) * 4;
            const float* src = qkv + (size_t)(b * N_TOK + m0 + r) * 1536 + 512 + h * 64 + cc;
            cp16(s_ks + (uint32_t)((buf * 4096 + r * 64 + (cc ^ ((r & 7) << 2))) * 4), src);
            cp16(s_vs + (uint32_t)((buf * 4096 + r * 64 + (cc ^ ((r & 3) << 3))) * 4), src + 512);
        }
        #pragma unroll
        for (int u = 0; u < 2; u++) {
            int f = tid + u * 128; int r = f >> 2; int cc = (f & 3) * 16;
            cp16(s_ms + (uint32_t)(buf * 4096 + r * 64 + cc),
                 mask + (size_t)b * N_TOK * N_TOK + (size_t)(n0 + r) * N_TOK + m0 + cc);
        }
        if (tid < 32)
            cp16(s_kc + (uint32_t)((buf * 128 + tid * 4) * 4),
                 coords + (size_t)(b * N_TOK + m0) * 2 + tid * 4);
    };

    issue(0, 0); cp_commit();

    // q coords for this thread's two rows
    const int qr0 = n0 + warp * 16 + g;
    float2 qc0 = *(const float2*)(coords + (size_t)(b * N_TOK + qr0) * 2);
    float2 qc1 = *(const float2*)(coords + (size_t)(b * N_TOK + qr0 + 8) * 2);

    // stage Q (scaled) into Ps, extract tf32 A-fragments into registers
    #pragma unroll
    for (int u = 0; u < 8; u++) {
        int f = tid + u * 128; int r = f >> 4; int cc = (f & 15) * 4;
        float4 v = *(const float4*)(qkv + (size_t)(b * N_TOK + n0 + r) * 1536 + h * 64 + cc);
        v.x *= 0.125f; v.y *= 0.125f; v.z *= 0.125f; v.w *= 0.125f;
        *(float4*)(Ps + r * 64 + (cc ^ ((r & 7) << 2))) = v;
    }
    __syncthreads();
    uint32_t Qf[8][4];
    {
        const int r0 = warp * 16 + g, sw = g << 2;
        #pragma unroll
        for (int ks = 0; ks < 8; ks++) {
            int c = ks * 8 + t;
            Qf[ks][0] = f2tf(Ps[r0 * 64 + (c ^ sw)]);
            Qf[ks][1] = f2tf(Ps[(r0 + 8) * 64 + (c ^ sw)]);
            Qf[ks][2] = f2tf(Ps[r0 * 64 + ((c + 4) ^ sw)]);
            Qf[ks][3] = f2tf(Ps[(r0 + 8) * 64 + ((c + 4) ^ sw)]);
        }
    }

    float O[8][4];
    #pragma unroll
    for (int nt = 0; nt < 8; nt++)
        #pragma unroll
        for (int e = 0; e < 4; e++) O[nt][e] = 0.0f;
    float m0r = -3.0e38f, m1r = -3.0e38f, l0 = 0.0f, l1 = 0.0f;

    for (int it = 0; it < 16; it++) {
        const int buf = it & 1;
        if (it + 1 < 16) { issue(buf ^ 1, (it + 1) * 64); cp_commit(); cp_wait<1>(); }
        else cp_wait<0>();
        __syncthreads();

        const float* Kb = Ks + buf * 4096;
        const float* Vb = Vs + buf * 4096;
        const float* kcb = kc + buf * 128;
        const unsigned char* Msb = Ms + buf * 4096;

        // S = Q @ K^T
        float S[8][4];
        #pragma unroll
        for (int nt = 0; nt < 8; nt++)
            #pragma unroll
            for (int e = 0; e < 4; e++) S[nt][e] = 0.0f;
        #pragma unroll
        for (int ks = 0; ks < 8; ks++) {
            int c = ks * 8 + t, sw = g << 2;
            #pragma unroll
            for (int nt = 0; nt < 8; nt++) {
                uint32_t bb[2];
                bb[0] = f2tf(Kb[(nt * 8 + g) * 64 + (c ^ sw)]);
                bb[1] = f2tf(Kb[(nt * 8 + g) * 64 + ((c + 4) ^ sw)]);
                mma_tf32(S[nt], Qf[ks], bb);
            }
        }

        // bias + mask + running max
        float mx0 = -3.0e38f, mx1 = -3.0e38f;
        #pragma unroll
        for (int nt = 0; nt < 8; nt++) {
            int cb = nt * 8 + 2 * t;
            float2 k0c = *(const float2*)(kcb + cb * 2);
            float2 k1c = *(const float2*)(kcb + cb * 2 + 2);
            uchar2 mk0 = *(const uchar2*)(Msb + (warp * 16 + g) * 64 + cb);
            uchar2 mk1 = *(const uchar2*)(Msb + (warp * 16 + g + 8) * 64 + cb);
            float dx, dy;
            dx = qc0.x - k0c.x; dy = qc0.y - k0c.y; float d00 = sqrtf(dx*dx + dy*dy);
            dx = qc0.x - k1c.x; dy = qc0.y - k1c.y; float d01 = sqrtf(dx*dx + dy*dy);
            dx = qc1.x - k0c.x; dy = qc1.y - k0c.y; float d10 = sqrtf(dx*dx + dy*dy);
            dx = qc1.x - k1c.x; dy = qc1.y - k1c.y; float d11 = sqrtf(dx*dx + dy*dy);
            S[nt][0] = mk0.x ? -1e9f : fmaf(d00, we, S[nt][0]);
            S[nt][1] = mk0.y ? -1e9f : fmaf(d01, we, S[nt][1]);
            S[nt][2] = mk1.x ? -1e9f : fmaf(d10, we, S[nt][2]);
            S[nt][3] = mk1.y ? -1e9f : fmaf(d11, we, S[nt][3]);
            mx0 = fmaxf(mx0, fmaxf(S[nt][0], S[nt][1]));
            mx1 = fmaxf(mx1, fmaxf(S[nt][2], S[nt][3]));
        }
        mx0 = fmaxf(mx0, __shfl_xor_sync(0xffffffffu, mx0, 1));
        mx0 = fmaxf(mx0, __shfl_xor_sync(0xffffffffu, mx0, 2));
        mx1 = fmaxf(mx1, __shfl_xor_sync(0xffffffffu, mx1, 1));
        mx1 = fmaxf(mx1, __shfl_xor_sync(0xffffffffu, mx1, 2));

        float mn0 = fmaxf(m0r, mx0), mn1 = fmaxf(m1r, mx1);
        float cr0 = __expf(m0r - mn0), cr1 = __expf(m1r - mn1);
        m0r = mn0; m1r = mn1;
        float s0 = 0.0f, s1 = 0.0f;
        #pragma unroll
        for (int nt = 0; nt < 8; nt++) {
            S[nt][0] = __expf(S[nt][0] - mn0);
            S[nt][1] = __expf(S[nt][1] - mn0);
            S[nt][2] = __expf(S[nt][2] - mn1);
            S[nt][3] = __expf(S[nt][3] - mn1);
            s0 += S[nt][0] + S[nt][1];
            s1 += S[nt][2] + S[nt][3];
        }
        s0 += __shfl_xor_sync(0xffffffffu, s0, 1);
        s0 += __shfl_xor_sync(0xffffffffu, s0, 2);
        s1 += __shfl_xor_sync(0xffffffffu, s1, 1);
        s1 += __shfl_xor_sync(0xffffffffu, s1, 2);
        l0 = l0 * cr0 + s0;
        l1 = l1 * cr1 + s1;
        #pragma unroll
        for (int nt = 0; nt < 8; nt++) {
            O[nt][0] *= cr0; O[nt][1] *= cr0; O[nt][2] *= cr1; O[nt][3] *= cr1;
        }

        // stage P through warp-private smem slice, then O += P @ V
        float* Pw = Ps + warp * 1024;
        __syncwarp();
        #pragma unroll
        for (int nt = 0; nt < 8; nt++) {
            int cb = (nt * 8 + 2 * t) ^ (g << 2);
            *(float2*)(Pw + g * 64 + cb)       = make_float2(S[nt][0], S[nt][1]);
            *(float2*)(Pw + (g + 8) * 64 + cb) = make_float2(S[nt][2], S[nt][3]);
        }
        __syncwarp();
        #pragma unroll
        for (int ks = 0; ks < 8; ks++) {
            int c = ks * 8 + t, sw = g << 2;
            uint32_t a[4];
            a[0] = f2tf(Pw[g * 64 + (c ^ sw)]);
            a[1] = f2tf(Pw[(g + 8) * 64 + (c ^ sw)]);
            a[2] = f2tf(Pw[g * 64 + ((c + 4) ^ sw)]);
            a[3] = f2tf(Pw[(g + 8) * 64 + ((c + 4) ^ sw)]);
            #pragma unroll
            for (int nt = 0; nt < 8; nt++) {
                uint32_t bb[2];
                int col = (nt * 8 + g) ^ (t << 3);
                bb[0] = f2tf(Vb[(ks * 8 + t) * 64 + col]);
                bb[1] = f2tf(Vb[(ks * 8 + t + 4) * 64 + col]);
                mma_tf32(O[nt], a, bb);
            }
        }
        __syncthreads();
    }

    const float i0 = 1.0f / l0, i1 = 1.0f / l1;
    #pragma unroll
    for (int nt = 0; nt < 8; nt++) {
        int col = h * 64 + nt * 8 + 2 * t;
        size_t r0 = (size_t)(b * N_TOK + n0 + warp * 16 + g) * D_MODEL + col;
        *(float2*)(out + r0)               = make_float2(O[nt][0] * i0, O[nt][1] * i0);
        *(float2*)(out + r0 + 8 * D_MODEL) = make_float2(O[nt][2] * i1, O[nt][3] * i1);
    }
}

// ---------------- launch ---------------------------------------------------------
extern "C" void kernel_launch(void* const* d_in, const int* in_sizes, int n_in,
                              void* d_out, int out_size) {
    const float* x      = (const float*)d_in[0];
    const float* coords = (const float*)d_in[1];
    const unsigned char* mask = (const unsigned char*)d_in[2];
    const float* ln1g = (const float*)d_in[3];
    const float* ln1b = (const float*)d_in[4];
    const float* wqkv = (const float*)d_in[5];
    const float* bqkv = (const float*)d_in[6];
    const float* wedge= (const float*)d_in[7];
    const float* wout = (const float*)d_in[8];
    const float* bout = (const float*)d_in[9];
    const float* ln2g = (const float*)d_in[10];
    const float* ln2b = (const float*)d_in[11];
    const float* w1   = (const float*)d_in[12];
    const float* b1   = (const float*)d_in[13];
    const float* w2   = (const float*)d_in[14];
    const float* b2   = (const float*)d_in[15];
    float* out = (float*)d_out;

    void *p;
    float *xln, *qkv, *att, *x2, *hid;
    cudaGetSymbolAddress(&p, g_xln); xln = (float*)p;
    cudaGetSymbolAddress(&p, g_qkv); qkv = (float*)p;
    cudaGetSymbolAddress(&p, g_att); att = (float*)p;
    cudaGetSymbolAddress(&p, g_x2);  x2  = (float*)p;
    cudaGetSymbolAddress(&p, g_hid); hid = (float*)p;

    const int ATTN_SMEM   = (2*4096 + 2*4096 + 4096 + 256) * 4 + 2 * 4096;  // 91136
    const int GEMM_SMEM_L = 2 * (128 * 32 + 32 * 128) * 4;                  // 65536
    const int GEMM_SMEM_S = 2 * (64 * 32 + 32 * 64) * 4;                    // 32768
    cudaFuncSetAttribute(attn_mma, cudaFuncAttributeMaxDynamicSharedMemorySize, ATTN_SMEM);
    cudaFuncSetAttribute(gemm_tf32<128,128,2,4,256>, cudaFuncAttributeMaxDynamicSharedMemorySize, GEMM_SMEM_L);
    cudaFuncSetAttribute(gemm_tf32<64,64,2,2,128>,   cudaFuncAttributeMaxDynamicSharedMemorySize, GEMM_SMEM_S);

    // 1) LN1
    ln_kernel<<<M_ROWS, 256>>>(x, ln1g, ln1b, xln);
    // 2) QKV: (2048,1536,512)
    gemm_tf32<128,128,2,4,256><<<dim3(1536/128, M_ROWS/128), 256, GEMM_SMEM_L>>>(
        xln, wqkv, bqkv, nullptr, qkv, M_ROWS, 1536, D_MODEL, 0);
    // 3) attention (tensor-core)
    attn_mma<<<dim3(N_TOK/64, HEADS, BATCH), 128, ATTN_SMEM>>>(qkv, coords, mask, wedge, att);
    // 4) out proj + residual(token_embs)
    gemm_tf32<64,64,2,2,128><<<dim3(D_MODEL/64, M_ROWS/64), 128, GEMM_SMEM_S>>>(
        att, wout, bout, x, x2, M_ROWS, D_MODEL, D_MODEL, 0);
    // 5) LN2
    ln_kernel<<<M_ROWS, 256>>>(x2, ln2g, ln2b, xln);
    // 6) fc1 + gelu
    gemm_tf32<128,128,2,4,256><<<dim3(HIDDEN/128, M_ROWS/128), 256, GEMM_SMEM_L>>>(
        xln, w1, b1, nullptr, hid, M_ROWS, HIDDEN, D_MODEL, 1);
    // 7) fc2 + residual(x2) -> out
    gemm_tf32<64,64,2,2,128><<<dim3(D_MODEL/64, M_ROWS/64), 128, GEMM_SMEM_S>>>(
        hid, w2, b2, x2, out, M_ROWS, D_MODEL, HIDDEN, 0);
}

// round 4
// speedup vs baseline: 3.2138x; 1.2103x over previous
#include <cuda_runtime.h>
#include <math.h>
#include <stdint.h>

#define D_MODEL 512
#define N_TOK   1024
#define BATCH   2
#define HEADS   8
#define HIDDEN  2048
#define M_ROWS  (BATCH * N_TOK)   // 2048

// ---------------- scratch (static device globals; no allocation) ----------------
__device__ __align__(256) float g_xln[M_ROWS * D_MODEL];
__device__ __align__(256) float g_qkv[M_ROWS * 3 * D_MODEL];
__device__ __align__(256) float g_att[M_ROWS * D_MODEL];
__device__ __align__(256) float g_x2 [M_ROWS * D_MODEL];
__device__ __align__(256) float g_hid[M_ROWS * HIDDEN];

// ---------------- helpers --------------------------------------------------------
__device__ __forceinline__ void cp16(uint32_t smem, const void* g) {
    asm volatile("cp.async.cg.shared.global [%0], [%1], 16;" :: "r"(smem), "l"(g));
}
__device__ __forceinline__ void cp_commit() { asm volatile("cp.async.commit_group;"); }
template<int N> __device__ __forceinline__ void cp_wait() {
    asm volatile("cp.async.wait_group %0;" :: "n"(N));
}
// TF32 tensor cores round fp32 operands internally; pass raw bits.
__device__ __forceinline__ uint32_t f2b(float x) { return __float_as_uint(x); }
__device__ __forceinline__ void mma_tf32(float c[4], const uint32_t a[4], const uint32_t b[2]) {
    asm volatile(
        "mma.sync.aligned.m16n8k8.row.col.f32.tf32.tf32.f32 "
        "{%0,%1,%2,%3}, {%4,%5,%6,%7}, {%8,%9}, {%0,%1,%2,%3};"
        : "+f"(c[0]), "+f"(c[1]), "+f"(c[2]), "+f"(c[3])
        : "r"(a[0]), "r"(a[1]), "r"(a[2]), "r"(a[3]), "r"(b[0]), "r"(b[1]));
}

// ---------------- LayerNorm ------------------------------------------------------
__global__ void ln_kernel(const float* __restrict__ x, const float* __restrict__ g,
                          const float* __restrict__ b, float* __restrict__ y) {
    int row = blockIdx.x;
    const float* xr = x + (size_t)row * D_MODEL;
    int t = threadIdx.x;
    float v0 = xr[t];
    float v1 = xr[t + 256];

    __shared__ float sh[8], sh2[8];
    int w = t >> 5, lane = t & 31;

    float s = v0 + v1;
    #pragma unroll
    for (int o = 16; o; o >>= 1) s += __shfl_xor_sync(0xffffffffu, s, o);
    if (lane == 0) sh[w] = s;
    __syncthreads();
    float mean = (sh[0]+sh[1]+sh[2]+sh[3]+sh[4]+sh[5]+sh[6]+sh[7]) * (1.0f / D_MODEL);

    float d0 = v0 - mean, d1 = v1 - mean;
    float q = d0 * d0 + d1 * d1;
    #pragma unroll
    for (int o = 16; o; o >>= 1) q += __shfl_xor_sync(0xffffffffu, q, o);
    if (lane == 0) sh2[w] = q;
    __syncthreads();
    float var = (sh2[0]+sh2[1]+sh2[2]+sh2[3]+sh2[4]+sh2[5]+sh2[6]+sh2[7]) * (1.0f / D_MODEL);
    float inv = rsqrtf(var + 1e-5f);

    float* yr = y + (size_t)row * D_MODEL;
    yr[t]       = d0 * inv * g[t]       + b[t];
    yr[t + 256] = d1 * inv * g[t + 256] + b[t + 256];
}

// ---------------- tf32 tensor-core GEMM ------------------------------------------
template<int BM, int BN, int WARPS_M, int WARPS_N, int THREADS>
__global__ void __launch_bounds__(THREADS) gemm_tf32(
        const float* __restrict__ A, const float* __restrict__ B,
        const float* __restrict__ bias, const float* __restrict__ res,
        float* __restrict__ C, int M, int Nn, int K, int do_gelu) {
    constexpr int BK = 32;
    constexpr int WM = BM / WARPS_M;
    constexpr int WN = BN / WARPS_N;
    constexpr int MT = WM / 16;
    constexpr int NT = WN / 8;

    extern __shared__ float sm[];
    float* As = sm;                        // [2][BM][BK]
    float* Bs = sm + 2 * BM * BK;          // [2][BK][BN]

    const int tid  = threadIdx.x;
    const int warp = tid >> 5;
    const int lane = tid & 31;
    const int gpid = lane >> 2;
    const int tgid = lane & 3;
    const int wm = warp / WARPS_N;
    const int wn = warp % WARPS_N;
    const int m0 = blockIdx.y * BM;
    const int n0 = blockIdx.x * BN;

    const uint32_t s_as = (uint32_t)__cvta_generic_to_shared(As);
    const uint32_t s_bs = (uint32_t)__cvta_generic_to_shared(Bs);

    float acc[MT][NT][4];
    #pragma unroll
    for (int i = 0; i < MT; i++)
        #pragma unroll
        for (int j = 0; j < NT; j++)
            #pragma unroll
            for (int e = 0; e < 4; e++) acc[i][j][e] = 0.0f;

    auto loadA = [&](int buf, int k0) {
        constexpr int RA = THREADS / 8;
        #pragma unroll
        for (int u = 0; u < BM / RA; u++) {
            int row = (tid >> 3) + u * RA;
            int g   = tid & 7;
            const float* src = A + (size_t)(m0 + row) * K + k0 + g * 4;
            uint32_t dst = s_as + (uint32_t)((buf * BM * BK + row * BK +
                                             ((g ^ (row & 7)) * 4)) * 4);
            cp16(dst, src);
        }
    };
    auto loadB = [&](int buf, int k0) {
        constexpr int CPR = BN / 4;
        constexpr int RPP = THREADS / CPR;
        #pragma unroll
        for (int u = 0; u < BK / RPP; u++) {
            int row = tid / CPR + u * RPP;
            int g   = tid % CPR;
            const float* src = B + (size_t)(k0 + row) * Nn + n0 + g * 4;
            uint32_t dst = s_bs + (uint32_t)((buf * BK * BN + row * BN +
                                             ((g ^ ((row & 3) << 1)) * 4)) * 4);
            cp16(dst, src);
        }
    };

    const int tiles = K >> 5;
    loadA(0, 0); loadB(0, 0); cp_commit();

    for (int kt = 0; kt < tiles; kt++) {
        const int cbuf = kt & 1;
        if (kt + 1 < tiles) {
            loadA(cbuf ^ 1, (kt + 1) * BK);
            loadB(cbuf ^ 1, (kt + 1) * BK);
            cp_commit();
            cp_wait<1>();
        } else {
            cp_wait<0>();
        }
        __syncthreads();

        const float* as = As + cbuf * BM * BK;
        const float* bs = Bs + cbuf * BK * BN;

        #pragma unroll
        for (int ks = 0; ks < 4; ks++) {
            const int k = ks * 8;
            uint32_t af[MT][4];
            #pragma unroll
            for (int mt = 0; mt < MT; mt++) {
                int r  = wm * WM + mt * 16 + gpid;
                int c  = k + tgid;
                int sw = (r & 7) << 2;
                af[mt][0] = f2b(as[r * BK + (c ^ sw)]);
                af[mt][1] = f2b(as[(r + 8) * BK + (c ^ sw)]);
                af[mt][2] = f2b(as[r * BK + ((c + 4) ^ sw)]);
                af[mt][3] = f2b(as[(r + 8) * BK + ((c + 4) ^ sw)]);
            }
            uint32_t bf[NT][2];
            #pragma unroll
            for (int nt = 0; nt < NT; nt++) {
                int n  = wn * WN + nt * 8 + gpid;
                int kk = k + tgid;
                int sw = (kk & 3) << 3;
                bf[nt][0] = f2b(bs[kk * BN + (n ^ sw)]);
                bf[nt][1] = f2b(bs[(kk + 4) * BN + (n ^ sw)]);
            }
            #pragma unroll
            for (int mt = 0; mt < MT; mt++)
                #pragma unroll
                for (int nt = 0; nt < NT; nt++)
                    mma_tf32(acc[mt][nt], af[mt], bf[nt]);
        }
        __syncthreads();
    }

    #pragma unroll
    for (int mt = 0; mt < MT; mt++) {
        #pragma unroll
        for (int nt = 0; nt < NT; nt++) {
            int r0 = m0 + wm * WM + mt * 16 + gpid;
            int c0 = n0 + wn * WN + nt * 8 + 2 * tgid;
            float bb0 = bias[c0], bb1 = bias[c0 + 1];
            float v00 = acc[mt][nt][0] + bb0, v01 = acc[mt][nt][1] + bb1;
            float v10 = acc[mt][nt][2] + bb0, v11 = acc[mt][nt][3] + bb1;
            if (do_gelu) {
                v00 = 0.5f * v00 * (1.0f + erff(v00 * 0.70710678118654752f));
                v01 = 0.5f * v01 * (1.0f + erff(v01 * 0.70710678118654752f));
                v10 = 0.5f * v10 * (1.0f + erff(v10 * 0.70710678118654752f));
                v11 = 0.5f * v11 * (1.0f + erff(v11 * 0.70710678118654752f));
            }
            if (res) {
                v00 += res[(size_t)r0 * Nn + c0];
                v01 += res[(size_t)r0 * Nn + c0 + 1];
                v10 += res[(size_t)(r0 + 8) * Nn + c0];
                v11 += res[(size_t)(r0 + 8) * Nn + c0 + 1];
            }
            *(float2*)(C + (size_t)r0 * Nn + c0)       = make_float2(v00, v01);
            *(float2*)(C + (size_t)(r0 + 8) * Nn + c0) = make_float2(v10, v11);
        }
    }
}

// ---------------- tf32 mma flash attention with distance bias --------------------
// bias[b,h,n,m] = ||coords[b,n]-coords[b,m]|| * w_edge[2,h]  (frame average collapses)
__global__ void __launch_bounds__(128) attn_mma(
        const float* __restrict__ qkv, const float* __restrict__ coords,
        const unsigned char* __restrict__ mask, const float* __restrict__ w_edge,
        float* __restrict__ out) {
    extern __shared__ float sm[];
    float* Ks = sm;                    // [2][64*64] swizzled c^((r&7)<<2)
    float* Vs = Ks + 2 * 4096;         // [2][64*64] swizzled c^((r&3)<<3)
    float* Ps = Vs + 2 * 4096;         // [64*64]  Q staging, then per-warp P
    float* kc = Ps + 4096;             // [2][128] key coords
    unsigned char* Ms = (unsigned char*)(kc + 256);  // [2][4096] mask tile

    const int b = blockIdx.z, h = blockIdx.y, n0 = blockIdx.x * 64;
    const int tid = threadIdx.x, warp = tid >> 5, lane = tid & 31;
    const int g = lane >> 2, t = lane & 3;
    const float we = w_edge[2 * HEADS + h];

    const uint32_t s_ks = (uint32_t)__cvta_generic_to_shared(Ks);
    const uint32_t s_vs = (uint32_t)__cvta_generic_to_shared(Vs);
    const uint32_t s_kc = (uint32_t)__cvta_generic_to_shared(kc);
    const uint32_t s_ms = (uint32_t)__cvta_generic_to_shared(Ms);

    auto issue = [&](int buf, int m0) {
        #pragma unroll
        for (int u = 0; u < 8; u++) {
            int f = tid + u * 128; int r = f >> 4; int cc = (f & 15) * 4;
            const float* src = qkv + (size_t)(b * N_TOK + m0 + r) * 1536 + 512 + h * 64 + cc;
            cp16(s_ks + (uint32_t)((buf * 4096 + r * 64 + (cc ^ ((r & 7) << 2))) * 4), src);
            cp16(s_vs + (uint32_t)((buf * 4096 + r * 64 + (cc ^ ((r & 3) << 3))) * 4), src + 512);
        }
        #pragma unroll
        for (int u = 0; u < 2; u++) {
            int f = tid + u * 128; int r = f >> 2; int cc = (f & 3) * 16;
            cp16(s_ms + (uint32_t)(buf * 4096 + r * 64 + cc),
                 mask + (size_t)b * N_TOK * N_TOK + (size_t)(n0 + r) * N_TOK + m0 + cc);
        }
        if (tid < 32)
            cp16(s_kc + (uint32_t)((buf * 128 + tid * 4) * 4),
                 coords + (size_t)(b * N_TOK + m0) * 2 + tid * 4);
    };

    issue(0, 0); cp_commit();

    const int qr0 = n0 + warp * 16 + g;
    float2 qc0 = *(const float2*)(coords + (size_t)(b * N_TOK + qr0) * 2);
    float2 qc1 = *(const float2*)(coords + (size_t)(b * N_TOK + qr0 + 8) * 2);

    // stage Q (scaled) into Ps, extract A-fragments into registers
    #pragma unroll
    for (int u = 0; u < 8; u++) {
        int f = tid + u * 128; int r = f >> 4; int cc = (f & 15) * 4;
        float4 v = *(const float4*)(qkv + (size_t)(b * N_TOK + n0 + r) * 1536 + h * 64 + cc);
        v.x *= 0.125f; v.y *= 0.125f; v.z *= 0.125f; v.w *= 0.125f;
        *(float4*)(Ps + r * 64 + (cc ^ ((r & 7) << 2))) = v;
    }
    __syncthreads();
    uint32_t Qf[8][4];
    {
        const int r0 = warp * 16 + g, sw = g << 2;
        #pragma unroll
        for (int ks = 0; ks < 8; ks++) {
            int c = ks * 8 + t;
            Qf[ks][0] = f2b(Ps[r0 * 64 + (c ^ sw)]);
            Qf[ks][1] = f2b(Ps[(r0 + 8) * 64 + (c ^ sw)]);
            Qf[ks][2] = f2b(Ps[r0 * 64 + ((c + 4) ^ sw)]);
            Qf[ks][3] = f2b(Ps[(r0 + 8) * 64 + ((c + 4) ^ sw)]);
        }
    }

    float O[8][4];
    #pragma unroll
    for (int nt = 0; nt < 8; nt++)
        #pragma unroll
        for (int e = 0; e < 4; e++) O[nt][e] = 0.0f;
    float m0r = -3.0e38f, m1r = -3.0e38f, l0 = 0.0f, l1 = 0.0f;

    for (int it = 0; it < 16; it++) {
        const int buf = it & 1;
        if (it + 1 < 16) { issue(buf ^ 1, (it + 1) * 64); cp_commit(); cp_wait<1>(); }
        else cp_wait<0>();
        __syncthreads();

        const float* Kb = Ks + buf * 4096;
        const float* Vb = Vs + buf * 4096;
        const float* kcb = kc + buf * 128;
        const unsigned char* Msb = Ms + buf * 4096;

        float S[8][4];
        #pragma unroll
        for (int nt = 0; nt < 8; nt++)
            #pragma unroll
            for (int e = 0; e < 4; e++) S[nt][e] = 0.0f;
        #pragma unroll
        for (int ks = 0; ks < 8; ks++) {
            int c = ks * 8 + t, sw = g << 2;
            #pragma unroll
            for (int nt = 0; nt < 8; nt++) {
                uint32_t bb[2];
                bb[0] = f2b(Kb[(nt * 8 + g) * 64 + (c ^ sw)]);
                bb[1] = f2b(Kb[(nt * 8 + g) * 64 + ((c + 4) ^ sw)]);
                mma_tf32(S[nt], Qf[ks], bb);
            }
        }

        float mx0 = -3.0e38f, mx1 = -3.0e38f;
        #pragma unroll
        for (int nt = 0; nt < 8; nt++) {
            int cb = nt * 8 + 2 * t;
            float2 k0c = *(const float2*)(kcb + cb * 2);
            float2 k1c = *(const float2*)(kcb + cb * 2 + 2);
            uchar2 mk0 = *(const uchar2*)(Msb + (warp * 16 + g) * 64 + cb);
            uchar2 mk1 = *(const uchar2*)(Msb + (warp * 16 + g + 8) * 64 + cb);
            float dx, dy;
            dx = qc0.x - k0c.x; dy = qc0.y - k0c.y; float d00 = sqrtf(dx*dx + dy*dy);
            dx = qc0.x - k1c.x; dy = qc0.y - k1c.y; float d01 = sqrtf(dx*dx + dy*dy);
            dx = qc1.x - k0c.x; dy = qc1.y - k0c.y; float d10 = sqrtf(dx*dx + dy*dy);
            dx = qc1.x - k1c.x; dy = qc1.y - k1c.y; float d11 = sqrtf(dx*dx + dy*dy);
            S[nt][0] = mk0.x ? -1e9f : fmaf(d00, we, S[nt][0]);
            S[nt][1] = mk0.y ? -1e9f : fmaf(d01, we, S[nt][1]);
            S[nt][2] = mk1.x ? -1e9f : fmaf(d10, we, S[nt][2]);
            S[nt][3] = mk1.y ? -1e9f : fmaf(d11, we, S[nt][3]);
            mx0 = fmaxf(mx0, fmaxf(S[nt][0], S[nt][1]));
            mx1 = fmaxf(mx1, fmaxf(S[nt][2], S[nt][3]));
        }
        mx0 = fmaxf(mx0, __shfl_xor_sync(0xffffffffu, mx0, 1));
        mx0 = fmaxf(mx0, __shfl_xor_sync(0xffffffffu, mx0, 2));
        mx1 = fmaxf(mx1, __shfl_xor_sync(0xffffffffu, mx1, 1));
        mx1 = fmaxf(mx1, __shfl_xor_sync(0xffffffffu, mx1, 2));

        float mn0 = fmaxf(m0r, mx0), mn1 = fmaxf(m1r, mx1);
        float cr0 = __expf(m0r - mn0), cr1 = __expf(m1r - mn1);
        m0r = mn0; m1r = mn1;
        float s0 = 0.0f, s1 = 0.0f;
        #pragma unroll
        for (int nt = 0; nt < 8; nt++) {
            S[nt][0] = __expf(S[nt][0] - mn0);
            S[nt][1] = __expf(S[nt][1] - mn0);
            S[nt][2] = __expf(S[nt][2] - mn1);
            S[nt][3] = __expf(S[nt][3] - mn1);
            s0 += S[nt][0] + S[nt][1];
            s1 += S[nt][2] + S[nt][3];
        }
        s0 += __shfl_xor_sync(0xffffffffu, s0, 1);
        s0 += __shfl_xor_sync(0xffffffffu, s0, 2);
        s1 += __shfl_xor_sync(0xffffffffu, s1, 1);
        s1 += __shfl_xor_sync(0xffffffffu, s1, 2);
        l0 = l0 * cr0 + s0;
        l1 = l1 * cr1 + s1;
        #pragma unroll
        for (int nt = 0; nt < 8; nt++) {
            O[nt][0] *= cr0; O[nt][1] *= cr0; O[nt][2] *= cr1; O[nt][3] *= cr1;
        }

        float* Pw = Ps + warp * 1024;
        __syncwarp();
        #pragma unroll
        for (int nt = 0; nt < 8; nt++) {
            int cb = (nt * 8 + 2 * t) ^ (g << 2);
            *(float2*)(Pw + g * 64 + cb)       = make_float2(S[nt][0], S[nt][1]);
            *(float2*)(Pw + (g + 8) * 64 + cb) = make_float2(S[nt][2], S[nt][3]);
        }
        __syncwarp();
        #pragma unroll
        for (int ks = 0; ks < 8; ks++) {
            int c = ks * 8 + t, sw = g << 2;
            uint32_t a[4];
            a[0] = f2b(Pw[g * 64 + (c ^ sw)]);
            a[1] = f2b(Pw[(g + 8) * 64 + (c ^ sw)]);
            a[2] = f2b(Pw[g * 64 + ((c + 4) ^ sw)]);
            a[3] = f2b(Pw[(g + 8) * 64 + ((c + 4) ^ sw)]);
            #pragma unroll
            for (int nt = 0; nt < 8; nt++) {
                uint32_t bb[2];
                int col = (nt * 8 + g) ^ (t << 3);
                bb[0] = f2b(Vb[(ks * 8 + t) * 64 + col]);
                bb[1] = f2b(Vb[(ks * 8 + t + 4) * 64 + col]);
                mma_tf32(O[nt], a, bb);
            }
        }
        __syncthreads();
    }

    const float i0 = 1.0f / l0, i1 = 1.0f / l1;
    #pragma unroll
    for (int nt = 0; nt < 8; nt++) {
        int col = h * 64 + nt * 8 + 2 * t;
        size_t r0 = (size_t)(b * N_TOK + n0 + warp * 16 + g) * D_MODEL + col;
        *(float2*)(out + r0)               = make_float2(O[nt][0] * i0, O[nt][1] * i0);
        *(float2*)(out + r0 + 8 * D_MODEL) = make_float2(O[nt][2] * i1, O[nt][3] * i1);
    }
}

// ---------------- launch ---------------------------------------------------------
extern "C" void kernel_launch(void* const* d_in, const int* in_sizes, int n_in,
                              void* d_out, int out_size) {
    const float* x      = (const float*)d_in[0];
    const float* coords = (const float*)d_in[1];
    const unsigned char* mask = (const unsigned char*)d_in[2];
    const float* ln1g = (const float*)d_in[3];
    const float* ln1b = (const float*)d_in[4];
    const float* wqkv = (const float*)d_in[5];
    const float* bqkv = (const float*)d_in[6];
    const float* wedge= (const float*)d_in[7];
    const float* wout = (const float*)d_in[8];
    const float* bout = (const float*)d_in[9];
    const float* ln2g = (const float*)d_in[10];
    const float* ln2b = (const float*)d_in[11];
    const float* w1   = (const float*)d_in[12];
    const float* b1   = (const float*)d_in[13];
    const float* w2   = (const float*)d_in[14];
    const float* b2   = (const float*)d_in[15];
    float* out = (float*)d_out;

    void *p;
    float *xln, *qkv, *att, *x2, *hid;
    cudaGetSymbolAddress(&p, g_xln); xln = (float*)p;
    cudaGetSymbolAddress(&p, g_qkv); qkv = (float*)p;
    cudaGetSymbolAddress(&p, g_att); att = (float*)p;
    cudaGetSymbolAddress(&p, g_x2);  x2  = (float*)p;
    cudaGetSymbolAddress(&p, g_hid); hid = (float*)p;

    const int ATTN_SMEM   = (2*4096 + 2*4096 + 4096 + 256) * 4 + 2 * 4096;  // 91136
    const int GEMM_SMEM_L = 2 * (128 * 32 + 32 * 64) * 4;                   // 49152
    const int GEMM_SMEM_S = 2 * (64 * 32 + 32 * 64) * 4;                    // 32768
    cudaFuncSetAttribute(attn_mma, cudaFuncAttributeMaxDynamicSharedMemorySize, ATTN_SMEM);
    cudaFuncSetAttribute(gemm_tf32<128,64,2,2,128>, cudaFuncAttributeMaxDynamicSharedMemorySize, GEMM_SMEM_L);
    cudaFuncSetAttribute(gemm_tf32<64,64,2,2,128>,  cudaFuncAttributeMaxDynamicSharedMemorySize, GEMM_SMEM_S);

    // 1) LN1
    ln_kernel<<<M_ROWS, 256>>>(x, ln1g, ln1b, xln);
    // 2) QKV: (2048,1536,512) — 384 blocks
    gemm_tf32<128,64,2,2,128><<<dim3(1536/64, M_ROWS/128), 128, GEMM_SMEM_L>>>(
        xln, wqkv, bqkv, nullptr, qkv, M_ROWS, 1536, D_MODEL, 0);
    // 3) attention (tensor-core)
    attn_mma<<<dim3(N_TOK/64, HEADS, BATCH), 128, ATTN_SMEM>>>(qkv, coords, mask, wedge, att);
    // 4) out proj + residual(token_embs) — 256 blocks
    gemm_tf32<64,64,2,2,128><<<dim3(D_MODEL/64, M_ROWS/64), 128, GEMM_SMEM_S>>>(
        att, wout, bout, x, x2, M_ROWS, D_MODEL, D_MODEL, 0);
    // 5) LN2
    ln_kernel<<<M_ROWS, 256>>>(x2, ln2g, ln2b, xln);
    // 6) fc1 + gelu — 512 blocks
    gemm_tf32<128,64,2,2,128><<<dim3(HIDDEN/64, M_ROWS/128), 128, GEMM_SMEM_L>>>(
        xln, w1, b1, nullptr, hid, M_ROWS, HIDDEN, D_MODEL, 1);
    // 7) fc2 + residual(x2) -> out — 256 blocks
    gemm_tf32<64,64,2,2,128><<<dim3(D_MODEL/64, M_ROWS/64), 128, GEMM_SMEM_S>>>(
        hid, w2, b2, x2, out, M_ROWS, D_MODEL, HIDDEN, 0);
}

// round 5
// speedup vs baseline: 3.5925x; 1.1178x over previous
#include <cuda_runtime.h>
#include <math.h>
#include <stdint.h>

#define D_MODEL 512
#define N_TOK   1024
#define BATCH   2
#define HEADS   8
#define HIDDEN  2048
#define M_ROWS  (BATCH * N_TOK)   // 2048

// ---------------- scratch (static device globals; no allocation) ----------------
__device__ __align__(256) float g_xln[M_ROWS * D_MODEL];
__device__ __align__(256) float g_qkv[M_ROWS * 3 * D_MODEL];
__device__ __align__(256) float g_vt [BATCH * HEADS * 64 * N_TOK];  // V^T per (b,h)
__device__ __align__(256) float g_att[M_ROWS * D_MODEL];
__device__ __align__(256) float g_x2 [M_ROWS * D_MODEL];
__device__ __align__(256) float g_hid[M_ROWS * HIDDEN];

// ---------------- helpers --------------------------------------------------------
__device__ __forceinline__ void cp16(uint32_t smem, const void* g) {
    asm volatile("cp.async.cg.shared.global [%0], [%1], 16;" :: "r"(smem), "l"(g));
}
__device__ __forceinline__ void cp_commit() { asm volatile("cp.async.commit_group;"); }
template<int N> __device__ __forceinline__ void cp_wait() {
    asm volatile("cp.async.wait_group %0;" :: "n"(N));
}
__device__ __forceinline__ uint32_t f2b(float x) { return __float_as_uint(x); }
__device__ __forceinline__ void mma_tf32(float c[4], const uint32_t a[4], const uint32_t b[2]) {
    asm volatile(
        "mma.sync.aligned.m16n8k8.row.col.f32.tf32.tf32.f32 "
        "{%0,%1,%2,%3}, {%4,%5,%6,%7}, {%8,%9}, {%0,%1,%2,%3};"
        : "+f"(c[0]), "+f"(c[1]), "+f"(c[2]), "+f"(c[3])
        : "r"(a[0]), "r"(a[1]), "r"(a[2]), "r"(a[3]), "r"(b[0]), "r"(b[1]));
}
// ldmatrix.x4 with b16 view of fp32 tiles: yields tf32 fragment layout directly
// (lane l -> float element at row l>>2, col l&3 of each 8x8-float matrix).
__device__ __forceinline__ void ldmx4(uint32_t r[4], uint32_t addr) {
    asm volatile("ldmatrix.sync.aligned.m8n8.x4.shared.b16 {%0,%1,%2,%3}, [%4];"
                 : "=r"(r[0]), "=r"(r[1]), "=r"(r[2]), "=r"(r[3]) : "r"(addr));
}
__device__ __forceinline__ float sqrt_approx(float x) {
    float r; asm("sqrt.approx.f32 %0, %1;" : "=f"(r) : "f"(x)); return r;
}

// ---------------- LayerNorm ------------------------------------------------------
__global__ void ln_kernel(const float* __restrict__ x, const float* __restrict__ g,
                          const float* __restrict__ b, float* __restrict__ y) {
    int row = blockIdx.x;
    const float* xr = x + (size_t)row * D_MODEL;
    int t = threadIdx.x;
    float v0 = xr[t];
    float v1 = xr[t + 256];

    __shared__ float sh[8], sh2[8];
    int w = t >> 5, lane = t & 31;

    float s = v0 + v1;
    #pragma unroll
    for (int o = 16; o; o >>= 1) s += __shfl_xor_sync(0xffffffffu, s, o);
    if (lane == 0) sh[w] = s;
    __syncthreads();
    float mean = (sh[0]+sh[1]+sh[2]+sh[3]+sh[4]+sh[5]+sh[6]+sh[7]) * (1.0f / D_MODEL);

    float d0 = v0 - mean, d1 = v1 - mean;
    float q = d0 * d0 + d1 * d1;
    #pragma unroll
    for (int o = 16; o; o >>= 1) q += __shfl_xor_sync(0xffffffffu, q, o);
    if (lane == 0) sh2[w] = q;
    __syncthreads();
    float var = (sh2[0]+sh2[1]+sh2[2]+sh2[3]+sh2[4]+sh2[5]+sh2[6]+sh2[7]) * (1.0f / D_MODEL);
    float inv = rsqrtf(var + 1e-5f);

    float* yr = y + (size_t)row * D_MODEL;
    yr[t]       = d0 * inv * g[t]       + b[t];
    yr[t + 256] = d1 * inv * g[t + 256] + b[t + 256];
}

// ---------------- V transpose: qkv V-slice -> g_vt[b,h][d][N] --------------------
__global__ void vtrans_kernel(const float* __restrict__ qkv, float* __restrict__ vt) {
    __shared__ float tile[64][65];
    const int n0 = blockIdx.x * 64;
    const int bh = blockIdx.y;
    const int b = bh >> 3, h = bh & 7;
    const int tid = threadIdx.x;

    #pragma unroll
    for (int u = 0; u < 4; u++) {
        int f = tid + u * 256;
        int nl = f >> 4, dc = (f & 15) * 4;
        float4 v = *(const float4*)(qkv + (size_t)(b * N_TOK + n0 + nl) * 1536 + 1024 + h * 64 + dc);
        tile[dc + 0][nl] = v.x;
        tile[dc + 1][nl] = v.y;
        tile[dc + 2][nl] = v.z;
        tile[dc + 3][nl] = v.w;
    }
    __syncthreads();
    #pragma unroll
    for (int u = 0; u < 4; u++) {
        int f = tid + u * 256;
        int dl = f >> 4, nc = (f & 15) * 4;
        float4 v = make_float4(tile[dl][nc], tile[dl][nc + 1], tile[dl][nc + 2], tile[dl][nc + 3]);
        *(float4*)(vt + (size_t)(bh * 64 + dl) * N_TOK + n0 + nc) = v;
    }
}

// ---------------- tf32 tensor-core GEMM (unchanged from R4) ----------------------
template<int BM, int BN, int WARPS_M, int WARPS_N, int THREADS>
__global__ void __launch_bounds__(THREADS) gemm_tf32(
        const float* __restrict__ A, const float* __restrict__ B,
        const float* __restrict__ bias, const float* __restrict__ res,
        float* __restrict__ C, int M, int Nn, int K, int do_gelu) {
    constexpr int BK = 32;
    constexpr int WM = BM / WARPS_M;
    constexpr int WN = BN / WARPS_N;
    constexpr int MT = WM / 16;
    constexpr int NT = WN / 8;

    extern __shared__ float sm[];
    float* As = sm;
    float* Bs = sm + 2 * BM * BK;

    const int tid  = threadIdx.x;
    const int warp = tid >> 5;
    const int lane = tid & 31;
    const int gpid = lane >> 2;
    const int tgid = lane & 3;
    const int wm = warp / WARPS_N;
    const int wn = warp % WARPS_N;
    const int m0 = blockIdx.y * BM;
    const int n0 = blockIdx.x * BN;

    const uint32_t s_as = (uint32_t)__cvta_generic_to_shared(As);
    const uint32_t s_bs = (uint32_t)__cvta_generic_to_shared(Bs);

    float acc[MT][NT][4];
    #pragma unroll
    for (int i = 0; i < MT; i++)
        #pragma unroll
        for (int j = 0; j < NT; j++)
            #pragma unroll
            for (int e = 0; e < 4; e++) acc[i][j][e] = 0.0f;

    auto loadA = [&](int buf, int k0) {
        constexpr int RA = THREADS / 8;
        #pragma unroll
        for (int u = 0; u < BM / RA; u++) {
            int row = (tid >> 3) + u * RA;
            int g   = tid & 7;
            const float* src = A + (size_t)(m0 + row) * K + k0 + g * 4;
            uint32_t dst = s_as + (uint32_t)((buf * BM * BK + row * BK +
                                             ((g ^ (row & 7)) * 4)) * 4);
            cp16(dst, src);
        }
    };
    auto loadB = [&](int buf, int k0) {
        constexpr int CPR = BN / 4;
        constexpr int RPP = THREADS / CPR;
        #pragma unroll
        for (int u = 0; u < BK / RPP; u++) {
            int row = tid / CPR + u * RPP;
            int g   = tid % CPR;
            const float* src = B + (size_t)(k0 + row) * Nn + n0 + g * 4;
            uint32_t dst = s_bs + (uint32_t)((buf * BK * BN + row * BN +
                                             ((g ^ ((row & 3) << 1)) * 4)) * 4);
            cp16(dst, src);
        }
    };

    const int tiles = K >> 5;
    loadA(0, 0); loadB(0, 0); cp_commit();

    for (int kt = 0; kt < tiles; kt++) {
        const int cbuf = kt & 1;
        if (kt + 1 < tiles) {
            loadA(cbuf ^ 1, (kt + 1) * BK);
            loadB(cbuf ^ 1, (kt + 1) * BK);
            cp_commit();
            cp_wait<1>();
        } else {
            cp_wait<0>();
        }
        __syncthreads();

        const float* as = As + cbuf * BM * BK;
        const float* bs = Bs + cbuf * BK * BN;

        #pragma unroll
        for (int ks = 0; ks < 4; ks++) {
            const int k = ks * 8;
            uint32_t af[MT][4];
            #pragma unroll
            for (int mt = 0; mt < MT; mt++) {
                int r  = wm * WM + mt * 16 + gpid;
                int c  = k + tgid;
                int sw = (r & 7) << 2;
                af[mt][0] = f2b(as[r * BK + (c ^ sw)]);
                af[mt][1] = f2b(as[(r + 8) * BK + (c ^ sw)]);
                af[mt][2] = f2b(as[r * BK + ((c + 4) ^ sw)]);
                af[mt][3] = f2b(as[(r + 8) * BK + ((c + 4) ^ sw)]);
            }
            uint32_t bf[NT][2];
            #pragma unroll
            for (int nt = 0; nt < NT; nt++) {
                int n  = wn * WN + nt * 8 + gpid;
                int kk = k + tgid;
                int sw = (kk & 3) << 3;
                bf[nt][0] = f2b(bs[kk * BN + (n ^ sw)]);
                bf[nt][1] = f2b(bs[(kk + 4) * BN + (n ^ sw)]);
            }
            #pragma unroll
            for (int mt = 0; mt < MT; mt++)
                #pragma unroll
                for (int nt = 0; nt < NT; nt++)
                    mma_tf32(acc[mt][nt], af[mt], bf[nt]);
        }
        __syncthreads();
    }

    #pragma unroll
    for (int mt = 0; mt < MT; mt++) {
        #pragma unroll
        for (int nt = 0; nt < NT; nt++) {
            int r0 = m0 + wm * WM + mt * 16 + gpid;
            int c0 = n0 + wn * WN + nt * 8 + 2 * tgid;
            float bb0 = bias[c0], bb1 = bias[c0 + 1];
            float v00 = acc[mt][nt][0] + bb0, v01 = acc[mt][nt][1] + bb1;
            float v10 = acc[mt][nt][2] + bb0, v11 = acc[mt][nt][3] + bb1;
            if (do_gelu) {
                v00 = 0.5f * v00 * (1.0f + erff(v00 * 0.70710678118654752f));
                v01 = 0.5f * v01 * (1.0f + erff(v01 * 0.70710678118654752f));
                v10 = 0.5f * v10 * (1.0f + erff(v10 * 0.70710678118654752f));
                v11 = 0.5f * v11 * (1.0f + erff(v11 * 0.70710678118654752f));
            }
            if (res) {
                v00 += res[(size_t)r0 * Nn + c0];
                v01 += res[(size_t)r0 * Nn + c0 + 1];
                v10 += res[(size_t)(r0 + 8) * Nn + c0];
                v11 += res[(size_t)(r0 + 8) * Nn + c0 + 1];
            }
            *(float2*)(C + (size_t)r0 * Nn + c0)       = make_float2(v00, v01);
            *(float2*)(C + (size_t)(r0 + 8) * Nn + c0) = make_float2(v10, v11);
        }
    }
}

// ---------------- tf32 mma flash attention, ldmatrix fragment loads --------------
// bias[b,h,n,m] = ||coords[b,n]-coords[b,m]|| * w_edge[2,h]  (frame average collapses)
__global__ void __launch_bounds__(128) attn_mma(
        const float* __restrict__ qkv, const float* __restrict__ vt,
        const float* __restrict__ coords, const unsigned char* __restrict__ mask,
        const float* __restrict__ w_edge, float* __restrict__ out) {
    extern __shared__ float sm[];
    float* Ks = sm;                    // [2][64 key][64 d]   chunk swizzle c^(r&7)
    float* Vs = Ks + 2 * 4096;         // [2][64 d][64 key]   chunk swizzle c^(r&7)
    float* Ps = Vs + 2 * 4096;         // [64][64] Q staging -> per-warp P slices
    float* kc = Ps + 4096;             // [2][128] key coords
    unsigned char* Ms = (unsigned char*)(kc + 256);  // [2][64][64] mask

    const int b = blockIdx.z, h = blockIdx.y, n0 = blockIdx.x * 64;
    const int bh = b * HEADS + h;
    const int tid = threadIdx.x, warp = tid >> 5, lane = tid & 31;
    const int g = lane >> 2, t = lane & 3;
    const int li = lane & 7, sel = lane >> 3;
    const float we = w_edge[2 * HEADS + h];

    const uint32_t s_ks = (uint32_t)__cvta_generic_to_shared(Ks);
    const uint32_t s_vs = (uint32_t)__cvta_generic_to_shared(Vs);
    const uint32_t s_ps = (uint32_t)__cvta_generic_to_shared(Ps);
    const uint32_t s_kc = (uint32_t)__cvta_generic_to_shared(kc);
    const uint32_t s_ms = (uint32_t)__cvta_generic_to_shared(Ms);

    auto issue = [&](int buf, int m0) {
        #pragma unroll
        for (int u = 0; u < 8; u++) {
            int f = tid + u * 128; int r = f >> 4; int c = f & 15;
            uint32_t off = (uint32_t)((buf * 4096 + r * 64 + ((c ^ (r & 7)) * 4)) * 4);
            cp16(s_ks + off, qkv + (size_t)(b * N_TOK + m0 + r) * 1536 + 512 + h * 64 + c * 4);
            cp16(s_vs + off, vt + (size_t)(bh * 64 + r) * N_TOK + m0 + c * 4);
        }
        #pragma unroll
        for (int u = 0; u < 2; u++) {
            int f = tid + u * 128; int r = f >> 2; int c = (f & 3) * 16;
            cp16(s_ms + (uint32_t)(buf * 4096 + r * 64 + c),
                 mask + (size_t)b * N_TOK * N_TOK + (size_t)(n0 + r) * N_TOK + m0 + c);
        }
        if (tid < 32)
            cp16(s_kc + (uint32_t)((buf * 128 + tid * 4) * 4),
                 coords + (size_t)(b * N_TOK + m0) * 2 + tid * 4);
    };

    issue(0, 0); cp_commit();

    const int qr0 = n0 + warp * 16 + g;
    float2 qc0 = *(const float2*)(coords + (size_t)(b * N_TOK + qr0) * 2);
    float2 qc1 = *(const float2*)(coords + (size_t)(b * N_TOK + qr0 + 8) * 2);

    // stage Q (scaled) into Ps, extract A-fragments via ldmatrix
    #pragma unroll
    for (int u = 0; u < 8; u++) {
        int f = tid + u * 128; int r = f >> 4; int c = f & 15;
        float4 v = *(const float4*)(qkv + (size_t)(b * N_TOK + n0 + r) * 1536 + h * 64 + c * 4);
        v.x *= 0.125f; v.y *= 0.125f; v.z *= 0.125f; v.w *= 0.125f;
        *(float4*)(Ps + r * 64 + ((c ^ (r & 7)) * 4)) = v;
    }
    __syncthreads();
    uint32_t Qf[8][4];
    {
        const int prow = warp * 16 + li + ((sel & 1) << 3);
        #pragma unroll
        for (int ks = 0; ks < 8; ks++) {
            int chunk = 2 * ks + (sel >> 1);
            ldmx4(Qf[ks], s_ps + (uint32_t)(prow * 256 + ((chunk ^ li) << 4)));
        }
    }

    float O[8][4];
    #pragma unroll
    for (int nt = 0; nt < 8; nt++)
        #pragma unroll
        for (int e = 0; e < 4; e++) O[nt][e] = 0.0f;
    float m0r = -3.0e38f, m1r = -3.0e38f, l0 = 0.0f, l1 = 0.0f;

    for (int it = 0; it < 16; it++) {
        const int buf = it & 1;
        if (it + 1 < 16) { issue(buf ^ 1, (it + 1) * 64); cp_commit(); cp_wait<1>(); }
        else cp_wait<0>();
        __syncthreads();

        const float* kcb = kc + buf * 128;
        const unsigned char* Msb = Ms + buf * 4096;

        // S = Q @ K^T  (K fragments via ldmatrix.x4: 2 k-steps per load)
        float S[8][4];
        #pragma unroll
        for (int nt = 0; nt < 8; nt++)
            #pragma unroll
            for (int e = 0; e < 4; e++) S[nt][e] = 0.0f;
        #pragma unroll
        for (int kp = 0; kp < 4; kp++) {
            uint32_t Kf[8][4];
            uint32_t base = s_ks + (uint32_t)(buf * 16384 + li * 256 +
                                             (((4 * kp + sel) ^ li) << 4));
            #pragma unroll
            for (int nt = 0; nt < 8; nt++) ldmx4(Kf[nt], base + nt * 2048);
            #pragma unroll
            for (int nt = 0; nt < 8; nt++) {
                mma_tf32(S[nt], Qf[2 * kp],     Kf[nt]);        // uses Kf[nt][0..1]
                mma_tf32(S[nt], Qf[2 * kp + 1], Kf[nt] + 2);    // uses Kf[nt][2..3]
            }
        }

        // bias + mask + running max
        float mx0 = -3.0e38f, mx1 = -3.0e38f;
        #pragma unroll
        for (int nt = 0; nt < 8; nt++) {
            int cb = nt * 8 + 2 * t;
            float2 k0c = *(const float2*)(kcb + cb * 2);
            float2 k1c = *(const float2*)(kcb + cb * 2 + 2);
            uchar2 mk0 = *(const uchar2*)(Msb + (warp * 16 + g) * 64 + cb);
            uchar2 mk1 = *(const uchar2*)(Msb + (warp * 16 + g + 8) * 64 + cb);
            float dx, dy;
            dx = qc0.x - k0c.x; dy = qc0.y - k0c.y; float d00 = sqrt_approx(dx*dx + dy*dy);
            dx = qc0.x - k1c.x; dy = qc0.y - k1c.y; float d01 = sqrt_approx(dx*dx + dy*dy);
            dx = qc1.x - k0c.x; dy = qc1.y - k0c.y; float d10 = sqrt_approx(dx*dx + dy*dy);
            dx = qc1.x - k1c.x; dy = qc1.y - k1c.y; float d11 = sqrt_approx(dx*dx + dy*dy);
            S[nt][0] = mk0.x ? -1e9f : fmaf(d00, we, S[nt][0]);
            S[nt][1] = mk0.y ? -1e9f : fmaf(d01, we, S[nt][1]);
            S[nt][2] = mk1.x ? -1e9f : fmaf(d10, we, S[nt][2]);
            S[nt][3] = mk1.y ? -1e9f : fmaf(d11, we, S[nt][3]);
            mx0 = fmaxf(mx0, fmaxf(S[nt][0], S[nt][1]));
            mx1 = fmaxf(mx1, fmaxf(S[nt][2], S[nt][3]));
        }
        mx0 = fmaxf(mx0, __shfl_xor_sync(0xffffffffu, mx0, 1));
        mx0 = fmaxf(mx0, __shfl_xor_sync(0xffffffffu, mx0, 2));
        mx1 = fmaxf(mx1, __shfl_xor_sync(0xffffffffu, mx1, 1));
        mx1 = fmaxf(mx1, __shfl_xor_sync(0xffffffffu, mx1, 2));

        float mn0 = fmaxf(m0r, mx0), mn1 = fmaxf(m1r, mx1);
        float cr0 = __expf(m0r - mn0), cr1 = __expf(m1r - mn1);
        m0r = mn0; m1r = mn1;
        float s0 = 0.0f, s1 = 0.0f;
        #pragma unroll
        for (int nt = 0; nt < 8; nt++) {
            S[nt][0] = __expf(S[nt][0] - mn0);
            S[nt][1] = __expf(S[nt][1] - mn0);
            S[nt][2] = __expf(S[nt][2] - mn1);
            S[nt][3] = __expf(S[nt][3] - mn1);
            s0 += S[nt][0] + S[nt][1];
            s1 += S[nt][2] + S[nt][3];
        }
        s0 += __shfl_xor_sync(0xffffffffu, s0, 1);
        s0 += __shfl_xor_sync(0xffffffffu, s0, 2);
        s1 += __shfl_xor_sync(0xffffffffu, s1, 1);
        s1 += __shfl_xor_sync(0xffffffffu, s1, 2);
        l0 = l0 * cr0 + s0;
        l1 = l1 * cr1 + s1;
        #pragma unroll
        for (int nt = 0; nt < 8; nt++) {
            O[nt][0] *= cr0; O[nt][1] *= cr0; O[nt][2] *= cr1; O[nt][3] *= cr1;
        }

        // store P into warp-private slice (chunk swizzle c^(row&7))
        float* Pw = Ps + warp * 1024;
        #pragma unroll
        for (int nt = 0; nt < 8; nt++) {
            int csw = (((2 * nt + (t >> 1)) ^ g) << 2) + ((t & 1) << 1);
            *(float2*)(Pw + g * 64 + csw)       = make_float2(S[nt][0], S[nt][1]);
            *(float2*)(Pw + (g + 8) * 64 + csw) = make_float2(S[nt][2], S[nt][3]);
        }
        __syncwarp();

        // O += P @ V  (P A-frags + V^T B-frags via ldmatrix.x4)
        const int prow = warp * 16 + li + ((sel & 1) << 3);
        #pragma unroll
        for (int kp = 0; kp < 4; kp++) {
            uint32_t Vf[8][4], Pa0[4], Pa1[4];
            uint32_t vbase = s_vs + (uint32_t)(buf * 16384 + li * 256 +
                                              (((4 * kp + sel) ^ li) << 4));
            #pragma unroll
            for (int nt = 0; nt < 8; nt++) ldmx4(Vf[nt], vbase + nt * 2048);
            {
                int c0 = 2 * (2 * kp)     + (sel >> 1);
                int c1 = 2 * (2 * kp + 1) + (sel >> 1);
                ldmx4(Pa0, s_ps + (uint32_t)(prow * 256 + ((c0 ^ li) << 4)));
                ldmx4(Pa1, s_ps + (uint32_t)(prow * 256 + ((c1 ^ li) << 4)));
            }
            #pragma unroll
            for (int nt = 0; nt < 8; nt++) {
                mma_tf32(O[nt], Pa0, Vf[nt]);       // Vf[nt][0..1]
                mma_tf32(O[nt], Pa1, Vf[nt] + 2);   // Vf[nt][2..3]
            }
        }
        __syncthreads();
    }

    const float i0 = 1.0f / l0, i1 = 1.0f / l1;
    #pragma unroll
    for (int nt = 0; nt < 8; nt++) {
        int col = h * 64 + nt * 8 + 2 * t;
        size_t r0 = (size_t)(b * N_TOK + n0 + warp * 16 + g) * D_MODEL + col;
        *(float2*)(out + r0)               = make_float2(O[nt][0] * i0, O[nt][1] * i0);
        *(float2*)(out + r0 + 8 * D_MODEL) = make_float2(O[nt][2] * i1, O[nt][3] * i1);
    }
}

// ---------------- launch ---------------------------------------------------------
extern "C" void kernel_launch(void* const* d_in, const int* in_sizes, int n_in,
                              void* d_out, int out_size) {
    const float* x      = (const float*)d_in[0];
    const float* coords = (const float*)d_in[1];
    const unsigned char* mask = (const unsigned char*)d_in[2];
    const float* ln1g = (const float*)d_in[3];
    const float* ln1b = (const float*)d_in[4];
    const float* wqkv = (const float*)d_in[5];
    const float* bqkv = (const float*)d_in[6];
    const float* wedge= (const float*)d_in[7];
    const float* wout = (const float*)d_in[8];
    const float* bout = (const float*)d_in[9];
    const float* ln2g = (const float*)d_in[10];
    const float* ln2b = (const float*)d_in[11];
    const float* w1   = (const float*)d_in[12];
    const float* b1   = (const float*)d_in[13];
    const float* w2   = (const float*)d_in[14];
    const float* b2   = (const float*)d_in[15];
    float* out = (float*)d_out;

    void *p;
    float *xln, *qkv, *vt, *att, *x2, *hid;
    cudaGetSymbolAddress(&p, g_xln); xln = (float*)p;
    cudaGetSymbolAddress(&p, g_qkv); qkv = (float*)p;
    cudaGetSymbolAddress(&p, g_vt);  vt  = (float*)p;
    cudaGetSymbolAddress(&p, g_att); att = (float*)p;
    cudaGetSymbolAddress(&p, g_x2);  x2  = (float*)p;
    cudaGetSymbolAddress(&p, g_hid); hid = (float*)p;

    const int ATTN_SMEM   = (2*4096 + 2*4096 + 4096 + 256) * 4 + 2 * 4096;  // 91136
    const int GEMM_SMEM_L = 2 * (128 * 32 + 32 * 64) * 4;                   // 49152
    const int GEMM_SMEM_S = 2 * (64 * 32 + 32 * 64) * 4;                    // 32768
    cudaFuncSetAttribute(attn_mma, cudaFuncAttributeMaxDynamicSharedMemorySize, ATTN_SMEM);
    cudaFuncSetAttribute(gemm_tf32<128,64,2,2,128>, cudaFuncAttributeMaxDynamicSharedMemorySize, GEMM_SMEM_L);
    cudaFuncSetAttribute(gemm_tf32<64,64,2,2,128>,  cudaFuncAttributeMaxDynamicSharedMemorySize, GEMM_SMEM_S);

    // 1) LN1
    ln_kernel<<<M_ROWS, 256>>>(x, ln1g, ln1b, xln);
    // 2) QKV
    gemm_tf32<128,64,2,2,128><<<dim3(1536/64, M_ROWS/128), 128, GEMM_SMEM_L>>>(
        xln, wqkv, bqkv, nullptr, qkv, M_ROWS, 1536, D_MODEL, 0);
    // 3) V transpose
    vtrans_kernel<<<dim3(N_TOK/64, BATCH*HEADS), 256>>>(qkv, vt);
    // 4) attention
    attn_mma<<<dim3(N_TOK/64, HEADS, BATCH), 128, ATTN_SMEM>>>(qkv, vt, coords, mask, wedge, att);
    // 5) out proj + residual(token_embs)
    gemm_tf32<64,64,2,2,128><<<dim3(D_MODEL/64, M_ROWS/64), 128, GEMM_SMEM_S>>>(
        att, wout, bout, x, x2, M_ROWS, D_MODEL, D_MODEL, 0);
    // 6) LN2
    ln_kernel<<<M_ROWS, 256>>>(x2, ln2g, ln2b, xln);
    // 7) fc1 + gelu
    gemm_tf32<128,64,2,2,128><<<dim3(HIDDEN/64, M_ROWS/128), 128, GEMM_SMEM_L>>>(
        xln, w1, b1, nullptr, hid, M_ROWS, HIDDEN, D_MODEL, 1);
    // 8) fc2 + residual(x2) -> out
    gemm_tf32<64,64,2,2,128><<<dim3(D_MODEL/64, M_ROWS/64), 128, GEMM_SMEM_S>>>(
        hid, w2, b2, x2, out, M_ROWS, D_MODEL, HIDDEN, 0);
}

// round 6
// speedup vs baseline: 3.9149x; 1.0897x over previous
#include <cuda_runtime.h>
#include <cuda_bf16.h>
#include <math.h>
#include <stdint.h>

#define D_MODEL 512
#define N_TOK   1024
#define BATCH   2
#define HEADS   8
#define HIDDEN  2048
#define M_ROWS  (BATCH * N_TOK)   // 2048

// ---------------- scratch (static device globals; no allocation) ----------------
__device__ __align__(256) float g_xln[M_ROWS * D_MODEL];
__device__ __align__(256) float g_qkv[M_ROWS * 3 * D_MODEL];
__device__ __align__(256) __nv_bfloat16 g_kp [BATCH * HEADS * N_TOK * 64];  // K  [bh][key][d]
__device__ __align__(256) __nv_bfloat16 g_vtp[BATCH * HEADS * 64 * N_TOK];  // V^T [bh][d][key]
__device__ __align__(256) float g_att[M_ROWS * D_MODEL];
__device__ __align__(256) float g_x2 [M_ROWS * D_MODEL];
__device__ __align__(256) float g_hid[M_ROWS * HIDDEN];

// ---------------- helpers --------------------------------------------------------
__device__ __forceinline__ void cp16(uint32_t smem, const void* g) {
    asm volatile("cp.async.cg.shared.global [%0], [%1], 16;" :: "r"(smem), "l"(g));
}
__device__ __forceinline__ void cp_commit() { asm volatile("cp.async.commit_group;"); }
template<int N> __device__ __forceinline__ void cp_wait() {
    asm volatile("cp.async.wait_group %0;" :: "n"(N));
}
__device__ __forceinline__ uint32_t f2b(float x) { return __float_as_uint(x); }
__device__ __forceinline__ uint32_t pkbf(float a, float b) {
    __nv_bfloat162 h = __floats2bfloat162_rn(a, b);
    return *(uint32_t*)&h;
}
__device__ __forceinline__ void mma_tf32(float c[4], const uint32_t a[4], const uint32_t b[2]) {
    asm volatile(
        "mma.sync.aligned.m16n8k8.row.col.f32.tf32.tf32.f32 "
        "{%0,%1,%2,%3}, {%4,%5,%6,%7}, {%8,%9}, {%0,%1,%2,%3};"
        : "+f"(c[0]), "+f"(c[1]), "+f"(c[2]), "+f"(c[3])
        : "r"(a[0]), "r"(a[1]), "r"(a[2]), "r"(a[3]), "r"(b[0]), "r"(b[1]));
}
__device__ __forceinline__ void mma_bf16(float c[4], const uint32_t a[4], const uint32_t b[2]) {
    asm volatile(
        "mma.sync.aligned.m16n8k16.row.col.f32.bf16.bf16.f32 "
        "{%0,%1,%2,%3}, {%4,%5,%6,%7}, {%8,%9}, {%0,%1,%2,%3};"
        : "+f"(c[0]), "+f"(c[1]), "+f"(c[2]), "+f"(c[3])
        : "r"(a[0]), "r"(a[1]), "r"(a[2]), "r"(a[3]), "r"(b[0]), "r"(b[1]));
}
__device__ __forceinline__ void ldmx4(uint32_t r[4], uint32_t addr) {
    asm volatile("ldmatrix.sync.aligned.m8n8.x4.shared.b16 {%0,%1,%2,%3}, [%4];"
                 : "=r"(r[0]), "=r"(r[1]), "=r"(r[2]), "=r"(r[3]) : "r"(addr));
}
__device__ __forceinline__ float sqrt_approx(float x) {
    float r; asm("sqrt.approx.f32 %0, %1;" : "=f"(r) : "f"(x)); return r;
}

// ---------------- LayerNorm ------------------------------------------------------
__global__ void ln_kernel(const float* __restrict__ x, const float* __restrict__ g,
                          const float* __restrict__ b, float* __restrict__ y) {
    int row = blockIdx.x;
    const float* xr = x + (size_t)row * D_MODEL;
    int t = threadIdx.x;
    float v0 = xr[t];
    float v1 = xr[t + 256];

    __shared__ float sh[8], sh2[8];
    int w = t >> 5, lane = t & 31;

    float s = v0 + v1;
    #pragma unroll
    for (int o = 16; o; o >>= 1) s += __shfl_xor_sync(0xffffffffu, s, o);
    if (lane == 0) sh[w] = s;
    __syncthreads();
    float mean = (sh[0]+sh[1]+sh[2]+sh[3]+sh[4]+sh[5]+sh[6]+sh[7]) * (1.0f / D_MODEL);

    float d0 = v0 - mean, d1 = v1 - mean;
    float q = d0 * d0 + d1 * d1;
    #pragma unroll
    for (int o = 16; o; o >>= 1) q += __shfl_xor_sync(0xffffffffu, q, o);
    if (lane == 0) sh2[w] = q;
    __syncthreads();
    float var = (sh2[0]+sh2[1]+sh2[2]+sh2[3]+sh2[4]+sh2[5]+sh2[6]+sh2[7]) * (1.0f / D_MODEL);
    float inv = rsqrtf(var + 1e-5f);

    float* yr = y + (size_t)row * D_MODEL;
    yr[t]       = d0 * inv * g[t]       + b[t];
    yr[t + 256] = d1 * inv * g[t + 256] + b[t + 256];
}

// ---------------- pack K (bf16 copy) + V^T (bf16 transpose) ----------------------
__global__ void pack_kv(const float* __restrict__ qkv,
                        __nv_bfloat16* __restrict__ kp,
                        __nv_bfloat16* __restrict__ vtp) {
    __shared__ float tile[64][65];
    const int n0 = blockIdx.x * 64;
    const int bh = blockIdx.y;
    const int b = bh >> 3, h = bh & 7;
    const int tid = threadIdx.x;

    // K: straight convert-copy, [bh][key][d]
    #pragma unroll
    for (int u = 0; u < 2; u++) {
        int f = tid + u * 256;
        int r = f >> 3, c = (f & 7) * 8;
        const float* src = qkv + (size_t)(b * N_TOK + n0 + r) * 1536 + 512 + h * 64 + c;
        float4 v0 = *(const float4*)src, v1 = *(const float4*)(src + 4);
        uint4 o;
        o.x = pkbf(v0.x, v0.y); o.y = pkbf(v0.z, v0.w);
        o.z = pkbf(v1.x, v1.y); o.w = pkbf(v1.z, v1.w);
        *(uint4*)(kp + (size_t)(bh * N_TOK + n0 + r) * 64 + c) = o;
    }

    // V: fp32 tile transpose then bf16 out, [bh][d][key]
    #pragma unroll
    for (int u = 0; u < 4; u++) {
        int f = tid + u * 256;
        int nl = f >> 4, dc = (f & 15) * 4;
        float4 v = *(const float4*)(qkv + (size_t)(b * N_TOK + n0 + nl) * 1536 + 1024 + h * 64 + dc);
        tile[dc + 0][nl] = v.x;
        tile[dc + 1][nl] = v.y;
        tile[dc + 2][nl] = v.z;
        tile[dc + 3][nl] = v.w;
    }
    __syncthreads();
    #pragma unroll
    for (int u = 0; u < 2; u++) {
        int f = tid + u * 256;
        int dl = f >> 3, nc = (f & 7) * 8;
        uint4 o;
        o.x = pkbf(tile[dl][nc + 0], tile[dl][nc + 1]);
        o.y = pkbf(tile[dl][nc + 2], tile[dl][nc + 3]);
        o.z = pkbf(tile[dl][nc + 4], tile[dl][nc + 5]);
        o.w = pkbf(tile[dl][nc + 6], tile[dl][nc + 7]);
        *(uint4*)(vtp + (size_t)(bh * 64 + dl) * N_TOK + n0 + nc) = o;
    }
}

// ---------------- tf32 tensor-core GEMM (unchanged) ------------------------------
template<int BM, int BN, int WARPS_M, int WARPS_N, int THREADS>
__global__ void __launch_bounds__(THREADS) gemm_tf32(
        const float* __restrict__ A, const float* __restrict__ B,
        const float* __restrict__ bias, const float* __restrict__ res,
        float* __restrict__ C, int M, int Nn, int K, int do_gelu) {
    constexpr int BK = 32;
    constexpr int WM = BM / WARPS_M;
    constexpr int WN = BN / WARPS_N;
    constexpr int MT = WM / 16;
    constexpr int NT = WN / 8;

    extern __shared__ float sm[];
    float* As = sm;
    float* Bs = sm + 2 * BM * BK;

    const int tid  = threadIdx.x;
    const int warp = tid >> 5;
    const int lane = tid & 31;
    const int gpid = lane >> 2;
    const int tgid = lane & 3;
    const int wm = warp / WARPS_N;
    const int wn = warp % WARPS_N;
    const int m0 = blockIdx.y * BM;
    const int n0 = blockIdx.x * BN;

    const uint32_t s_as = (uint32_t)__cvta_generic_to_shared(As);
    const uint32_t s_bs = (uint32_t)__cvta_generic_to_shared(Bs);

    float acc[MT][NT][4];
    #pragma unroll
    for (int i = 0; i < MT; i++)
        #pragma unroll
        for (int j = 0; j < NT; j++)
            #pragma unroll
            for (int e = 0; e < 4; e++) acc[i][j][e] = 0.0f;

    auto loadA = [&](int buf, int k0) {
        constexpr int RA = THREADS / 8;
        #pragma unroll
        for (int u = 0; u < BM / RA; u++) {
            int row = (tid >> 3) + u * RA;
            int g   = tid & 7;
            const float* src = A + (size_t)(m0 + row) * K + k0 + g * 4;
            uint32_t dst = s_as + (uint32_t)((buf * BM * BK + row * BK +
                                             ((g ^ (row & 7)) * 4)) * 4);
            cp16(dst, src);
        }
    };
    auto loadB = [&](int buf, int k0) {
        constexpr int CPR = BN / 4;
        constexpr int RPP = THREADS / CPR;
        #pragma unroll
        for (int u = 0; u < BK / RPP; u++) {
            int row = tid / CPR + u * RPP;
            int g   = tid % CPR;
            const float* src = B + (size_t)(k0 + row) * Nn + n0 + g * 4;
            uint32_t dst = s_bs + (uint32_t)((buf * BK * BN + row * BN +
                                             ((g ^ ((row & 3) << 1)) * 4)) * 4);
            cp16(dst, src);
        }
    };

    const int tiles = K >> 5;
    loadA(0, 0); loadB(0, 0); cp_commit();

    for (int kt = 0; kt < tiles; kt++) {
        const int cbuf = kt & 1;
        if (kt + 1 < tiles) {
            loadA(cbuf ^ 1, (kt + 1) * BK);
            loadB(cbuf ^ 1, (kt + 1) * BK);
            cp_commit();
            cp_wait<1>();
        } else {
            cp_wait<0>();
        }
        __syncthreads();

        const float* as = As + cbuf * BM * BK;
        const float* bs = Bs + cbuf * BK * BN;

        #pragma unroll
        for (int ks = 0; ks < 4; ks++) {
            const int k = ks * 8;
            uint32_t af[MT][4];
            #pragma unroll
            for (int mt = 0; mt < MT; mt++) {
                int r  = wm * WM + mt * 16 + gpid;
                int c  = k + tgid;
                int sw = (r & 7) << 2;
                af[mt][0] = f2b(as[r * BK + (c ^ sw)]);
                af[mt][1] = f2b(as[(r + 8) * BK + (c ^ sw)]);
                af[mt][2] = f2b(as[r * BK + ((c + 4) ^ sw)]);
                af[mt][3] = f2b(as[(r + 8) * BK + ((c + 4) ^ sw)]);
            }
            uint32_t bf[NT][2];
            #pragma unroll
            for (int nt = 0; nt < NT; nt++) {
                int n  = wn * WN + nt * 8 + gpid;
                int kk = k + tgid;
                int sw = (kk & 3) << 3;
                bf[nt][0] = f2b(bs[kk * BN + (n ^ sw)]);
                bf[nt][1] = f2b(bs[(kk + 4) * BN + (n ^ sw)]);
            }
            #pragma unroll
            for (int mt = 0; mt < MT; mt++)
                #pragma unroll
                for (int nt = 0; nt < NT; nt++)
                    mma_tf32(acc[mt][nt], af[mt], bf[nt]);
        }
        __syncthreads();
    }

    #pragma unroll
    for (int mt = 0; mt < MT; mt++) {
        #pragma unroll
        for (int nt = 0; nt < NT; nt++) {
            int r0 = m0 + wm * WM + mt * 16 + gpid;
            int c0 = n0 + wn * WN + nt * 8 + 2 * tgid;
            float bb0 = bias[c0], bb1 = bias[c0 + 1];
            float v00 = acc[mt][nt][0] + bb0, v01 = acc[mt][nt][1] + bb1;
            float v10 = acc[mt][nt][2] + bb0, v11 = acc[mt][nt][3] + bb1;
            if (do_gelu) {
                v00 = 0.5f * v00 * (1.0f + erff(v00 * 0.70710678118654752f));
                v01 = 0.5f * v01 * (1.0f + erff(v01 * 0.70710678118654752f));
                v10 = 0.5f * v10 * (1.0f + erff(v10 * 0.70710678118654752f));
                v11 = 0.5f * v11 * (1.0f + erff(v11 * 0.70710678118654752f));
            }
            if (res) {
                v00 += res[(size_t)r0 * Nn + c0];
                v01 += res[(size_t)r0 * Nn + c0 + 1];
                v10 += res[(size_t)(r0 + 8) * Nn + c0];
                v11 += res[(size_t)(r0 + 8) * Nn + c0 + 1];
            }
            *(float2*)(C + (size_t)r0 * Nn + c0)       = make_float2(v00, v01);
            *(float2*)(C + (size_t)(r0 + 8) * Nn + c0) = make_float2(v10, v11);
        }
    }
}

// ---------------- bf16 mma flash attention ---------------------------------------
// bias[b,h,n,m] = ||coords[b,n]-coords[b,m]|| * w_edge[2,h]  (frame average collapses)
// smem byte layout (all bf16 tiles are [rows][128B], chunk swizzle c^(r&7)):
//   Ks  [2][64 key][64 d]   @ 0      (16384 B)
//   Vs  [2][64 d][64 key]   @ 16384  (16384 B)
//   Ps  Q staging [64][64] then per-warp P [16][64] @ 32768 (8192 B)
//   kc  [2][128] floats     @ 40960  (1024 B)
//   Ms  [2][64][64] bytes   @ 41984  (8192 B)   total 50176 B
__global__ void __launch_bounds__(128) attn_bf16(
        const float* __restrict__ qkv, const __nv_bfloat16* __restrict__ kp,
        const __nv_bfloat16* __restrict__ vtp, const float* __restrict__ coords,
        const unsigned char* __restrict__ mask, const float* __restrict__ w_edge,
        float* __restrict__ out) {
    extern __shared__ char smb[];
    const uint32_t S0 = (uint32_t)__cvta_generic_to_shared(smb);
    const uint32_t OKS = S0, OVS = S0 + 16384, OPS = S0 + 32768;
    const uint32_t OKC = S0 + 40960, OMS = S0 + 41984;

    const int b = blockIdx.z, h = blockIdx.y, n0 = blockIdx.x * 64;
    const int bh = b * HEADS + h;
    const int tid = threadIdx.x, warp = tid >> 5, lane = tid & 31;
    const int g = lane >> 2, t = lane & 3;
    const int l7 = lane & 7, sel = lane >> 3;
    const float we = w_edge[2 * HEADS + h];

    auto issue = [&](int buf, int m0) {
        #pragma unroll
        for (int u = 0; u < 4; u++) {
            int f = tid + u * 128; int r = f >> 3; int c = f & 7;
            uint32_t off = (uint32_t)(buf * 8192 + r * 128 + ((c ^ (r & 7)) << 4));
            cp16(OKS + off, kp  + (size_t)(bh * N_TOK + m0 + r) * 64 + c * 8);
            cp16(OVS + off, vtp + (size_t)(bh * 64 + r) * N_TOK + m0 + c * 8);
        }
        #pragma unroll
        for (int u = 0; u < 2; u++) {
            int f = tid + u * 128; int r = f >> 2; int c = (f & 3) * 16;
            cp16(OMS + (uint32_t)(buf * 4096 + r * 64 + c),
                 mask + (size_t)b * N_TOK * N_TOK + (size_t)(n0 + r) * N_TOK + m0 + c);
        }
        if (tid < 32)
            cp16(OKC + (uint32_t)(buf * 512 + tid * 16),
                 coords + (size_t)(b * N_TOK + m0) * 2 + tid * 4);
    };

    issue(0, 0); cp_commit();

    const int qr0 = n0 + warp * 16 + g;
    float2 qc0 = *(const float2*)(coords + (size_t)(b * N_TOK + qr0) * 2);
    float2 qc1 = *(const float2*)(coords + (size_t)(b * N_TOK + qr0 + 8) * 2);

    // stage Q (scaled, bf16) into Ps
    #pragma unroll
    for (int u = 0; u < 4; u++) {
        int f = tid + u * 128; int r = f >> 3; int c = f & 7;
        const float* src = qkv + (size_t)(b * N_TOK + n0 + r) * 1536 + h * 64 + c * 8;
        float4 v0 = *(const float4*)src, v1 = *(const float4*)(src + 4);
        uint4 o;
        o.x = pkbf(v0.x * 0.125f, v0.y * 0.125f);
        o.y = pkbf(v0.z * 0.125f, v0.w * 0.125f);
        o.z = pkbf(v1.x * 0.125f, v1.y * 0.125f);
        o.w = pkbf(v1.z * 0.125f, v1.w * 0.125f);
        *(uint4*)(smb + 32768 + r * 128 + ((c ^ (r & 7)) << 4)) = o;
    }
    __syncthreads();

    // Q fragments: 4 k16-steps, held in registers for the whole kernel
    uint32_t Qf[4][4];
    {
        const int row = warp * 16 + l7 + ((sel & 1) << 3);
        #pragma unroll
        for (int ks = 0; ks < 4; ks++) {
            int chunk = 2 * ks + (sel >> 1);
            ldmx4(Qf[ks], OPS + (uint32_t)(row * 128 + ((chunk ^ (row & 7)) << 4)));
        }
    }

    float O[8][4];
    #pragma unroll
    for (int nt = 0; nt < 8; nt++)
        #pragma unroll
        for (int e = 0; e < 4; e++) O[nt][e] = 0.0f;
    float m0r = -3.0e38f, m1r = -3.0e38f, l0 = 0.0f, l1 = 0.0f;

    for (int it = 0; it < 16; it++) {
        const int buf = it & 1;
        if (it + 1 < 16) { issue(buf ^ 1, (it + 1) * 64); cp_commit(); cp_wait<1>(); }
        else cp_wait<0>();
        __syncthreads();

        const float* kcb = (const float*)(smb + 40960 + buf * 512);
        const unsigned char* Msb = (const unsigned char*)(smb + 41984 + buf * 4096);

        // S = Q @ K^T  (B-frags: 16 keys x 16 d per ldmatrix.x4)
        float S[8][4];
        #pragma unroll
        for (int nt = 0; nt < 8; nt++)
            #pragma unroll
            for (int e = 0; e < 4; e++) S[nt][e] = 0.0f;
        #pragma unroll
        for (int ks = 0; ks < 4; ks++) {
            #pragma unroll
            for (int np = 0; np < 4; np++) {
                uint32_t Kf[4];
                int row = np * 16 + l7 + ((sel >> 1) << 3);
                int chunk = 2 * ks + (sel & 1);
                ldmx4(Kf, OKS + (uint32_t)(buf * 8192 + row * 128 +
                                           ((chunk ^ (row & 7)) << 4)));
                mma_bf16(S[2 * np],     Qf[ks], Kf);
                mma_bf16(S[2 * np + 1], Qf[ks], Kf + 2);
            }
        }

        // bias + mask + running max
        float mx0 = -3.0e38f, mx1 = -3.0e38f;
        #pragma unroll
        for (int nt = 0; nt < 8; nt++) {
            int cb = nt * 8 + 2 * t;
            float2 k0c = *(const float2*)(kcb + cb * 2);
            float2 k1c = *(const float2*)(kcb + cb * 2 + 2);
            uchar2 mk0 = *(const uchar2*)(Msb + (warp * 16 + g) * 64 + cb);
            uchar2 mk1 = *(const uchar2*)(Msb + (warp * 16 + g + 8) * 64 + cb);
            float dx, dy;
            dx = qc0.x - k0c.x; dy = qc0.y - k0c.y; float d00 = sqrt_approx(dx*dx + dy*dy);
            dx = qc0.x - k1c.x; dy = qc0.y - k1c.y; float d01 = sqrt_approx(dx*dx + dy*dy);
            dx = qc1.x - k0c.x; dy = qc1.y - k0c.y; float d10 = sqrt_approx(dx*dx + dy*dy);
            dx = qc1.x - k1c.x; dy = qc1.y - k1c.y; float d11 = sqrt_approx(dx*dx + dy*dy);
            S[nt][0] = mk0.x ? -1e9f : fmaf(d00, we, S[nt][0]);
            S[nt][1] = mk0.y ? -1e9f : fmaf(d01, we, S[nt][1]);
            S[nt][2] = mk1.x ? -1e9f : fmaf(d10, we, S[nt][2]);
            S[nt][3] = mk1.y ? -1e9f : fmaf(d11, we, S[nt][3]);
            mx0 = fmaxf(mx0, fmaxf(S[nt][0], S[nt][1]));
            mx1 = fmaxf(mx1, fmaxf(S[nt][2], S[nt][3]));
        }
        mx0 = fmaxf(mx0, __shfl_xor_sync(0xffffffffu, mx0, 1));
        mx0 = fmaxf(mx0, __shfl_xor_sync(0xffffffffu, mx0, 2));
        mx1 = fmaxf(mx1, __shfl_xor_sync(0xffffffffu, mx1, 1));
        mx1 = fmaxf(mx1, __shfl_xor_sync(0xffffffffu, mx1, 2));

        float mn0 = fmaxf(m0r, mx0), mn1 = fmaxf(m1r, mx1);
        float cr0 = __expf(m0r - mn0), cr1 = __expf(m1r - mn1);
        m0r = mn0; m1r = mn1;
        float s0 = 0.0f, s1 = 0.0f;
        #pragma unroll
        for (int nt = 0; nt < 8; nt++) {
            S[nt][0] = __expf(S[nt][0] - mn0);
            S[nt][1] = __expf(S[nt][1] - mn0);
            S[nt][2] = __expf(S[nt][2] - mn1);
            S[nt][3] = __expf(S[nt][3] - mn1);
            s0 += S[nt][0] + S[nt][1];
            s1 += S[nt][2] + S[nt][3];
        }
        s0 += __shfl_xor_sync(0xffffffffu, s0, 1);
        s0 += __shfl_xor_sync(0xffffffffu, s0, 2);
        s1 += __shfl_xor_sync(0xffffffffu, s1, 1);
        s1 += __shfl_xor_sync(0xffffffffu, s1, 2);
        l0 = l0 * cr0 + s0;
        l1 = l1 * cr1 + s1;
        #pragma unroll
        for (int nt = 0; nt < 8; nt++) {
            O[nt][0] *= cr0; O[nt][1] *= cr0; O[nt][2] *= cr1; O[nt][3] *= cr1;
        }

        // pack P -> bf16 into warp-private slice [16 q][64 key] (rows 128B)
        {
            char* Pw = smb + 32768 + warp * 2048;
            #pragma unroll
            for (int nt = 0; nt < 8; nt++) {
                uint32_t p01 = pkbf(S[nt][0], S[nt][1]);
                uint32_t p23 = pkbf(S[nt][2], S[nt][3]);
                uint32_t sw = (uint32_t)(((nt ^ g) << 4) + t * 4);
                *(uint32_t*)(Pw + g * 128 + sw)       = p01;
                *(uint32_t*)(Pw + (g + 8) * 128 + sw) = p23;
            }
        }
        __syncwarp();

        // O += P @ V  (A: P frags; B: V^T frags — 16 keys x 16 d per x4)
        #pragma unroll
        for (int kk = 0; kk < 4; kk++) {
            uint32_t Pa[4];
            {
                int row = l7 + ((sel & 1) << 3);
                int chunk = 2 * kk + (sel >> 1);
                ldmx4(Pa, OPS + (uint32_t)(warp * 2048 + row * 128 +
                                           ((chunk ^ (row & 7)) << 4)));
            }
            #pragma unroll
            for (int dp = 0; dp < 4; dp++) {
                uint32_t Vf[4];
                int row = dp * 16 + l7 + ((sel >> 1) << 3);
                int chunk = 2 * kk + (sel & 1);
                ldmx4(Vf, OVS + (uint32_t)(buf * 8192 + row * 128 +
                                           ((chunk ^ (row & 7)) << 4)));
                mma_bf16(O[2 * dp],     Pa, Vf);
                mma_bf16(O[2 * dp + 1], Pa, Vf + 2);
            }
        }
        __syncthreads();
    }

    const float i0 = 1.0f / l0, i1 = 1.0f / l1;
    #pragma unroll
    for (int nt = 0; nt < 8; nt++) {
        int col = h * 64 + nt * 8 + 2 * t;
        size_t r0 = (size_t)(b * N_TOK + n0 + warp * 16 + g) * D_MODEL + col;
        *(float2*)(out + r0)               = make_float2(O[nt][0] * i0, O[nt][1] * i0);
        *(float2*)(out + r0 + 8 * D_MODEL) = make_float2(O[nt][2] * i1, O[nt][3] * i1);
    }
}

// ---------------- launch ---------------------------------------------------------
extern "C" void kernel_launch(void* const* d_in, const int* in_sizes, int n_in,
                              void* d_out, int out_size) {
    const float* x      = (const float*)d_in[0];
    const float* coords = (const float*)d_in[1];
    const unsigned char* mask = (const unsigned char*)d_in[2];
    const float* ln1g = (const float*)d_in[3];
    const float* ln1b = (const float*)d_in[4];
    const float* wqkv = (const float*)d_in[5];
    const float* bqkv = (const float*)d_in[6];
    const float* wedge= (const float*)d_in[7];
    const float* wout = (const float*)d_in[8];
    const float* bout = (const float*)d_in[9];
    const float* ln2g = (const float*)d_in[10];
    const float* ln2b = (const float*)d_in[11];
    const float* w1   = (const float*)d_in[12];
    const float* b1   = (const float*)d_in[13];
    const float* w2   = (const float*)d_in[14];
    const float* b2   = (const float*)d_in[15];
    float* out = (float*)d_out;

    void *p;
    float *xln, *qkv, *att, *x2, *hid;
    __nv_bfloat16 *kp, *vtp;
    cudaGetSymbolAddress(&p, g_xln); xln = (float*)p;
    cudaGetSymbolAddress(&p, g_qkv); qkv = (float*)p;
    cudaGetSymbolAddress(&p, g_kp);  kp  = (__nv_bfloat16*)p;
    cudaGetSymbolAddress(&p, g_vtp); vtp = (__nv_bfloat16*)p;
    cudaGetSymbolAddress(&p, g_att); att = (float*)p;
    cudaGetSymbolAddress(&p, g_x2);  x2  = (float*)p;
    cudaGetSymbolAddress(&p, g_hid); hid = (float*)p;

    const int ATTN_SMEM   = 50176;
    const int GEMM_SMEM_L = 2 * (128 * 32 + 32 * 64) * 4;   // 49152
    const int GEMM_SMEM_S = 2 * (64 * 32 + 32 * 64) * 4;    // 32768
    cudaFuncSetAttribute(attn_bf16, cudaFuncAttributeMaxDynamicSharedMemorySize, ATTN_SMEM);
    cudaFuncSetAttribute(gemm_tf32<128,64,2,2,128>, cudaFuncAttributeMaxDynamicSharedMemorySize, GEMM_SMEM_L);
    cudaFuncSetAttribute(gemm_tf32<64,64,2,2,128>,  cudaFuncAttributeMaxDynamicSharedMemorySize, GEMM_SMEM_S);

    // 1) LN1
    ln_kernel<<<M_ROWS, 256>>>(x, ln1g, ln1b, xln);
    // 2) QKV
    gemm_tf32<128,64,2,2,128><<<dim3(1536/64, M_ROWS/128), 128, GEMM_SMEM_L>>>(
        xln, wqkv, bqkv, nullptr, qkv, M_ROWS, 1536, D_MODEL, 0);
    // 3) pack K/V to bf16 (+ V transpose)
    pack_kv<<<dim3(N_TOK/64, BATCH*HEADS), 256>>>(qkv, kp, vtp);
    // 4) attention (bf16 mma)
    attn_bf16<<<dim3(N_TOK/64, HEADS, BATCH), 128, ATTN_SMEM>>>(
        qkv, kp, vtp, coords, mask, wedge, att);
    // 5) out proj + residual(token_embs)
    gemm_tf32<64,64,2,2,128><<<dim3(D_MODEL/64, M_ROWS/64), 128, GEMM_SMEM_S>>>(
        att, wout, bout, x, x2, M_ROWS, D_MODEL, D_MODEL, 0);
    // 6) LN2
    ln_kernel<<<M_ROWS, 256>>>(x2, ln2g, ln2b, xln);
    // 7) fc1 + gelu
    gemm_tf32<128,64,2,2,128><<<dim3(HIDDEN/64, M_ROWS/128), 128, GEMM_SMEM_L>>>(
        xln, w1, b1, nullptr, hid, M_ROWS, HIDDEN, D_MODEL, 1);
    // 8) fc2 + residual(x2) -> out
    gemm_tf32<64,64,2,2,128><<<dim3(D_MODEL/64, M_ROWS/64), 128, GEMM_SMEM_S>>>(
        hid, w2, b2, x2, out, M_ROWS, D_MODEL, HIDDEN, 0);
}